// round 14
// baseline (speedup 1.0000x reference)
#include <cuda_runtime.h>
#include <cuda_fp16.h>
#include <math.h>
#include <stdint.h>

#define B_   256
#define S_   500
#define T_   (B_*S_)        // 128000
#define DQ_  128
#define DV_  256
#define M_   50
#define F_   512
#define NEA_ 512
#define KEA_ 256
#define KRO_ 384
#define LML_ 64
#define USTR 80

// ---------------- scratch (device globals) ----------------
__device__ __half g_bufX [2*T_*DQ_];
__device__ __half g_bufX3[T_*DQ_];
__device__ __half g_bufTD[T_*DQ_];
__device__ __half g_bufQA[T_*DV_];
__device__ __half g_bufEA[T_*NEA_];
__device__ __half g_PredIn[T_*KRO_];
__device__ float  g_logits[T_*LML_];
__device__ float  g_predP[4][T_];
__device__ float  g_accum[2];
__device__ __half g_Wea[NEA_*KEA_];
__device__ __half g_Wd1[DQ_*DQ_];
__device__ __half g_Wd2[DQ_*DQ_];
__device__ __half g_Wro[F_*KRO_];
__device__ __half g_Wmk[128*DQ_];
__device__ float  g_bea[NEA_];

// ==================== helpers ====================
__device__ __forceinline__ int ph(int d) {
    int pair = d >> 1;
    int pi   = pair & 15;
    int pp   = (pair & ~15) | ((pi & 3) * 4 + (pi >> 2));
    return pp * 2 + (d & 1);
}
__device__ __forceinline__ int permc(int cn) {
    int pair = cn >> 1;
    int pi   = pair & 15;
    int pp   = (pair & ~15) | ((pi & 3) * 4 + (pi >> 2));
    return pp * 2;
}
__device__ __forceinline__ float fsig(float x) { return 1.f / (1.f + __expf(-x)); }
__device__ __forceinline__ float ftanh(float x) {
    float ax = fabsf(x);
    float t  = 1.f - 2.f / (1.f + __expf(2.f * ax));
    return copysignf(t, x);
}
__device__ __forceinline__ void mma16(float* d,
    uint32_t a0, uint32_t a1, uint32_t a2, uint32_t a3,
    uint32_t b0, uint32_t b1)
{
    asm volatile(
        "mma.sync.aligned.m16n8k16.row.col.f32.f16.f16.f32 "
        "{%0,%1,%2,%3},{%4,%5,%6,%7},{%8,%9},{%0,%1,%2,%3};"
        : "+f"(d[0]), "+f"(d[1]), "+f"(d[2]), "+f"(d[3])
        : "r"(a0), "r"(a1), "r"(a2), "r"(a3), "r"(b0), "r"(b1));
}
__device__ __forceinline__ void cpa16(uint32_t dst, const void* src) {
    asm volatile("cp.async.cg.shared.global [%0], [%1], 16;" :: "r"(dst), "l"(src));
}
// packed f32x2
__device__ __forceinline__ unsigned long long pk2(float lo, float hi) {
    unsigned long long r;
    asm("mov.b64 %0, {%1, %2};" : "=l"(r) : "f"(lo), "f"(hi));
    return r;
}
__device__ __forceinline__ float2 upk2(unsigned long long v) {
    float2 r;
    asm("mov.b64 {%0, %1}, %2;" : "=f"(r.x), "=f"(r.y) : "l"(v));
    return r;
}
__device__ __forceinline__ unsigned long long fma2(
    unsigned long long a, unsigned long long b, unsigned long long c)
{
    unsigned long long d;
    asm("fma.rn.f32x2 %0, %1, %2, %3;" : "=l"(d) : "l"(a), "l"(b), "l"(c));
    return d;
}

// ==================== device GEMM body: EA (K=256, perm store) ==============
__device__ __forceinline__ void dev_ea(uint32_t* sm, int m0, int n0,
    const __half* __restrict__ A, const __half* __restrict__ W,
    const float* __restrict__ bias, __half* __restrict__ C)
{
    constexpr int NCH = 8, LDP = 128;
    uint32_t* As = sm;
    uint32_t* Bs = sm + 3 * 2048;

    const int tid  = threadIdx.x;
    const int lane = tid & 31, w = tid >> 5;
    const int g    = lane >> 2, c = lane & 3;
    const int wm0  = (w >> 2) * 64;
    const int wn0  = (w & 3) * 32;
    const int srow = tid >> 2;
    const int grp  = tid & 3;

    const uint32_t* Ag = (const uint32_t*)A + (size_t)(m0 + srow) * LDP + grp * 4;
    const uint32_t* Wg = (const uint32_t*)W + (size_t)(n0 + srow) * LDP + grp * 4;
    const uint32_t asb = (uint32_t)__cvta_generic_to_shared(As) + (srow * 16 + grp * 4) * 4;
    const uint32_t bsb = (uint32_t)__cvta_generic_to_shared(Bs) + (srow * 16 + grp * 4) * 4;

    float acc[4][4][4];
    #pragma unroll
    for (int i = 0; i < 4; i++)
        #pragma unroll
        for (int j = 0; j < 4; j++)
            #pragma unroll
            for (int r = 0; r < 4; r++) acc[i][j][r] = 0.f;

    auto stage = [&](int ch, int s) {
        uint32_t ab = asb + s * 2048 * 4;
        cpa16(ab,               Ag + ch * 16);
        cpa16(ab + 64 * 16 * 4, Ag + (size_t)64 * LDP + ch * 16);
        uint32_t bb = bsb + s * 2048 * 4;
        cpa16(bb,               Wg + ch * 16);
        cpa16(bb + 64 * 16 * 4, Wg + (size_t)64 * LDP + ch * 16);
        asm volatile("cp.async.commit_group;");
    };

    stage(0, 0); stage(1, 1);
    #pragma unroll
    for (int ch = 0; ch < NCH; ch++) {
        asm volatile("cp.async.wait_group 1;");
        __syncthreads();
        if (ch + 2 < NCH) stage(ch + 2, (ch + 2) % 3);
        else asm volatile("cp.async.commit_group;");
        const uint32_t* as = As + (ch % 3) * 2048;
        const uint32_t* bs = Bs + (ch % 3) * 2048;
        uint4 alo[4], ahi[4];
        #pragma unroll
        for (int mi = 0; mi < 4; mi++) {
            alo[mi] = *(const uint4*)&as[(wm0 + mi*16 + g)     * 16 + c*4];
            ahi[mi] = *(const uint4*)&as[(wm0 + mi*16 + g + 8) * 16 + c*4];
        }
        #pragma unroll
        for (int ni = 0; ni < 4; ni++) {
            uint4 b = *(const uint4*)&bs[(wn0 + ni*8 + g) * 16 + c*4];
            #pragma unroll
            for (int mi = 0; mi < 4; mi++) {
                mma16(acc[mi][ni], alo[mi].x, ahi[mi].x, alo[mi].y, ahi[mi].y, b.x, b.y);
                mma16(acc[mi][ni], alo[mi].z, ahi[mi].z, alo[mi].w, ahi[mi].w, b.z, b.w);
            }
        }
    }

    #pragma unroll
    for (int ni = 0; ni < 4; ni++) {
        int cn  = n0 + wn0 + ni*8 + c*2;
        int cnp = permc(cn);
        float b0 = __ldg(&bias[cn]), b1 = __ldg(&bias[cn+1]);
        #pragma unroll
        for (int mi = 0; mi < 4; mi++) {
            int r0 = m0 + wm0 + mi*16 + g;
            float v0 = acc[mi][ni][0] + b0, v1 = acc[mi][ni][1] + b1;
            float v2 = acc[mi][ni][2] + b0, v3 = acc[mi][ni][3] + b1;
            if (cn < DV_) { v0 = fsig(v0); v1 = fsig(v1); v2 = fsig(v2); v3 = fsig(v3); }
            else          { v0 = ftanh(v0); v1 = ftanh(v1); v2 = ftanh(v2); v3 = ftanh(v3); }
            *(__half2*)&C[(size_t)r0    *NEA_ + cnp] = __floats2half2_rn(v0, v1);
            *(__half2*)&C[(size_t)(r0+8)*NEA_ + cnp] = __floats2half2_rn(v2, v3);
        }
    }
}

// ==================== device body: lin12 ====================
__device__ __forceinline__ void dev_lin12(uint32_t* sm, int m0,
    const __half* __restrict__ A,
    const __half* __restrict__ W1, const __half* __restrict__ W2,
    const float* __restrict__ b1, const float* __restrict__ b2,
    __half* __restrict__ TD, __half* __restrict__ X3,
    const int* __restrict__ q_data, const int* __restrict__ attempt_data,
    const int* __restrict__ hint_data, const int* __restrict__ hintTotal_data,
    const float* __restrict__ q_emb, const float* __restrict__ attempt_emb,
    const float* __restrict__ ht_emb)
{
    uint32_t* Xs = sm;
    uint32_t* Bs = sm + 3*2048;
    uint32_t* Us = sm + 6*2048;

    const int tid  = threadIdx.x;
    const int lane = tid & 31, w = tid >> 5;
    const int g    = lane >> 2, c = lane & 3;
    const int wm0  = (w >> 2) * 64;
    const int wn0  = (w & 3) * 32;
    const int srow = tid >> 2;
    const int grp  = tid & 3;

    const uint32_t* Ag  = (const uint32_t*)A  + (size_t)(m0 + srow) * 64 + grp * 4;
    const uint32_t* W1g = (const uint32_t*)W1 + (size_t)srow * 64 + grp * 4;
    const uint32_t* W2g = (const uint32_t*)W2 + (size_t)srow * 64 + grp * 4;

    const uint32_t xsb = (uint32_t)__cvta_generic_to_shared(Xs) + (srow*16 + grp*4) * 4;
    const uint32_t bsb = (uint32_t)__cvta_generic_to_shared(Bs) + (srow*16 + grp*4) * 4;

    float acc[4][4][4];
    #pragma unroll
    for (int i = 0; i < 4; i++)
        #pragma unroll
        for (int j = 0; j < 4; j++)
            #pragma unroll
            for (int r = 0; r < 4; r++) acc[i][j][r] = 0.f;

    auto stage1 = [&](int ch, int s) {
        uint32_t xb = xsb + s * 2048 * 4;
        cpa16(xb,           Ag + ch * 16);
        cpa16(xb + 64*16*4, Ag + (size_t)64*64 + ch * 16);
        uint32_t bb = bsb + s * 2048 * 4;
        cpa16(bb,           W1g + ch * 16);
        cpa16(bb + 64*16*4, W1g + (size_t)64*64 + ch * 16);
        asm volatile("cp.async.commit_group;");
    };

    stage1(0, 0); stage1(1, 1);
    #pragma unroll
    for (int ch = 0; ch < 4; ch++) {
        asm volatile("cp.async.wait_group 1;");
        __syncthreads();
        if (ch + 2 < 4) stage1(ch + 2, (ch + 2) % 3);
        else asm volatile("cp.async.commit_group;");
        const uint32_t* xs = Xs + (ch % 3) * 2048;
        const uint32_t* bs = Bs + (ch % 3) * 2048;
        uint4 alo[4], ahi[4];
        #pragma unroll
        for (int mi = 0; mi < 4; mi++) {
            alo[mi] = *(const uint4*)&xs[(wm0 + mi*16 + g)     * 16 + c*4];
            ahi[mi] = *(const uint4*)&xs[(wm0 + mi*16 + g + 8) * 16 + c*4];
        }
        #pragma unroll
        for (int ni = 0; ni < 4; ni++) {
            uint4 b = *(const uint4*)&bs[(wn0 + ni*8 + g) * 16 + c*4];
            #pragma unroll
            for (int mi = 0; mi < 4; mi++) {
                mma16(acc[mi][ni], alo[mi].x, ahi[mi].x, alo[mi].y, ahi[mi].y, b.x, b.y);
                mma16(acc[mi][ni], alo[mi].z, ahi[mi].z, alo[mi].w, ahi[mi].w, b.z, b.w);
            }
        }
    }
    asm volatile("cp.async.wait_group 0;");

    #pragma unroll
    for (int ni = 0; ni < 4; ni++) {
        int cn = wn0 + ni*8 + c*2;
        float bb0 = __ldg(&b1[cn]), bb1 = __ldg(&b1[cn+1]);
        int pw = permc(cn) >> 1;
        #pragma unroll
        for (int mi = 0; mi < 4; mi++) {
            int r0 = wm0 + mi*16 + g;
            __half2 h0 = __floats2half2_rn(ftanh(acc[mi][ni][0] + bb0), ftanh(acc[mi][ni][1] + bb1));
            __half2 h1 = __floats2half2_rn(ftanh(acc[mi][ni][2] + bb0), ftanh(acc[mi][ni][3] + bb1));
            Us[r0*USTR + pw]     = *(uint32_t*)&h0;
            Us[(r0+8)*USTR + pw] = *(uint32_t*)&h1;
            acc[mi][ni][0] = acc[mi][ni][1] = acc[mi][ni][2] = acc[mi][ni][3] = 0.f;
        }
    }
    __syncthreads();

    auto stage2 = [&](int ch, int s) {
        uint32_t bb = bsb + s * 2048 * 4;
        cpa16(bb,           W2g + ch * 16);
        cpa16(bb + 64*16*4, W2g + (size_t)64*64 + ch * 16);
        asm volatile("cp.async.commit_group;");
    };
    stage2(0, 0); stage2(1, 1);
    #pragma unroll
    for (int ch = 0; ch < 4; ch++) {
        asm volatile("cp.async.wait_group 1;");
        __syncthreads();
        if (ch + 2 < 4) stage2(ch + 2, (ch + 2) % 3);
        else asm volatile("cp.async.commit_group;");
        const uint32_t* bs = Bs + (ch % 3) * 2048;
        uint4 alo[4], ahi[4];
        #pragma unroll
        for (int mi = 0; mi < 4; mi++) {
            alo[mi] = *(const uint4*)&Us[(wm0 + mi*16 + g)     * USTR + ch*16 + c*4];
            ahi[mi] = *(const uint4*)&Us[(wm0 + mi*16 + g + 8) * USTR + ch*16 + c*4];
        }
        #pragma unroll
        for (int ni = 0; ni < 4; ni++) {
            uint4 b = *(const uint4*)&bs[(wn0 + ni*8 + g) * 16 + c*4];
            #pragma unroll
            for (int mi = 0; mi < 4; mi++) {
                mma16(acc[mi][ni], alo[mi].x, ahi[mi].x, alo[mi].y, ahi[mi].y, b.x, b.y);
                mma16(acc[mi][ni], alo[mi].z, ahi[mi].z, alo[mi].w, ahi[mi].w, b.z, b.w);
            }
        }
    }

    const bool isdiff = (m0 >= T_);
    #pragma unroll
    for (int mi = 0; mi < 4; mi++) {
        #pragma unroll
        for (int h = 0; h < 2; h++) {
            int r = wm0 + mi*16 + g + h*8;
            int t = m0 + r;
            if (!isdiff) {
                #pragma unroll
                for (int ni = 0; ni < 4; ni++) {
                    int cn = wn0 + ni*8 + c*2;
                    float v0 = fsig(acc[mi][ni][2*h]   + __ldg(&b2[cn]));
                    float v1 = fsig(acc[mi][ni][2*h+1] + __ldg(&b2[cn+1]));
                    *(__half2*)&TD[(size_t)t*DQ_ + cn] = __floats2half2_rn(v0, v1);
                }
            } else {
                int tt = t - T_;
                int qi = q_data[tt], ai = attempt_data[tt];
                int hi = hint_data[tt], hti = hintTotal_data[tt];
                #pragma unroll
                for (int ni = 0; ni < 4; ni++) {
                    int cn = wn0 + ni*8 + c*2;
                    float v0 = fsig(acc[mi][ni][2*h]   + __ldg(&b2[cn]));
                    float v1 = fsig(acc[mi][ni][2*h+1] + __ldg(&b2[cn+1]));
                    float qe0 = q_emb[(size_t)qi*DQ_ + cn],   qe1 = q_emb[(size_t)qi*DQ_ + cn+1];
                    float g0  = attempt_emb[(size_t)ai*DQ_ + cn]
                              + ht_emb[(size_t)hi*DQ_ + cn] + ht_emb[(size_t)hti*DQ_ + cn];
                    float g1  = attempt_emb[(size_t)ai*DQ_ + cn+1]
                              + ht_emb[(size_t)hi*DQ_ + cn+1] + ht_emb[(size_t)hti*DQ_ + cn+1];
                    *(__half2*)&X3[(size_t)tt*DQ_ + permc(cn)] =
                        __floats2half2_rn(fmaf(v0, g0, qe0), fmaf(v1, g1, qe1));
                }
            }
        }
    }
}

// ==================== device body: qplog ====================
__device__ __forceinline__ void dev_qplog(uint32_t* sm, int m0,
    const __half* __restrict__ A,
    const __half* __restrict__ W1, const __half* __restrict__ WM,
    const float* __restrict__ b1, const __half* __restrict__ TD,
    const int* __restrict__ time_data, const float* __restrict__ time_emb,
    __half* __restrict__ PredIn, float* __restrict__ logits)
{
    uint32_t* Xs  = sm;
    uint32_t* Bs  = sm + 3*2048;
    uint32_t* Us  = sm + 6*2048;
    float*    red = (float*)(sm + 6*2048 + 128*USTR);

    const int tid  = threadIdx.x;
    const int lane = tid & 31, w = tid >> 5;
    const int g    = lane >> 2, c = lane & 3;
    const int wm0  = (w >> 2) * 64;
    const int wn0  = (w & 3) * 32;
    const int srow = tid >> 2;
    const int grp  = tid & 3;

    const uint32_t* Ag  = (const uint32_t*)A  + (size_t)(m0 + srow) * 64 + grp * 4;
    const uint32_t* W1g = (const uint32_t*)W1 + (size_t)srow * 64 + grp * 4;
    const uint32_t* WMg = (const uint32_t*)WM + (size_t)srow * 64 + grp * 4;

    const uint32_t xsb = (uint32_t)__cvta_generic_to_shared(Xs) + (srow*16 + grp*4) * 4;
    const uint32_t bsb = (uint32_t)__cvta_generic_to_shared(Bs) + (srow*16 + grp*4) * 4;

    float acc[4][4][4];
    #pragma unroll
    for (int i = 0; i < 4; i++)
        #pragma unroll
        for (int j = 0; j < 4; j++)
            #pragma unroll
            for (int r = 0; r < 4; r++) acc[i][j][r] = 0.f;

    auto stage1 = [&](int ch, int s) {
        uint32_t xb = xsb + s * 2048 * 4;
        cpa16(xb,           Ag + ch * 16);
        cpa16(xb + 64*16*4, Ag + (size_t)64*64 + ch * 16);
        uint32_t bb = bsb + s * 2048 * 4;
        cpa16(bb,           W1g + ch * 16);
        cpa16(bb + 64*16*4, W1g + (size_t)64*64 + ch * 16);
        asm volatile("cp.async.commit_group;");
    };
    stage1(0, 0); stage1(1, 1);
    #pragma unroll
    for (int ch = 0; ch < 4; ch++) {
        asm volatile("cp.async.wait_group 1;");
        __syncthreads();
        if (ch + 2 < 4) stage1(ch + 2, (ch + 2) % 3);
        else asm volatile("cp.async.commit_group;");
        const uint32_t* xs = Xs + (ch % 3) * 2048;
        const uint32_t* bs = Bs + (ch % 3) * 2048;
        uint4 alo[4], ahi[4];
        #pragma unroll
        for (int mi = 0; mi < 4; mi++) {
            alo[mi] = *(const uint4*)&xs[(wm0 + mi*16 + g)     * 16 + c*4];
            ahi[mi] = *(const uint4*)&xs[(wm0 + mi*16 + g + 8) * 16 + c*4];
        }
        #pragma unroll
        for (int ni = 0; ni < 4; ni++) {
            uint4 b = *(const uint4*)&bs[(wn0 + ni*8 + g) * 16 + c*4];
            #pragma unroll
            for (int mi = 0; mi < 4; mi++) {
                mma16(acc[mi][ni], alo[mi].x, ahi[mi].x, alo[mi].y, ahi[mi].y, b.x, b.y);
                mma16(acc[mi][ni], alo[mi].z, ahi[mi].z, alo[mi].w, ahi[mi].w, b.z, b.w);
            }
        }
    }
    asm volatile("cp.async.wait_group 0;");

    #pragma unroll
    for (int mi = 0; mi < 4; mi++) {
        #pragma unroll
        for (int h = 0; h < 2; h++) {
            int r = wm0 + mi*16 + g + h*8;
            int t = m0 + r;
            int ti = time_data[t];
            #pragma unroll
            for (int ni = 0; ni < 4; ni++) {
                int cn = wn0 + ni*8 + c*2;
                float q0 = acc[mi][ni][2*h]   + __ldg(&b1[cn]);
                float q1 = acc[mi][ni][2*h+1] + __ldg(&b1[cn+1]);
                __half2 hq = __floats2half2_rn(q0, q1);
                Us[r*USTR + (permc(cn) >> 1)] = *(uint32_t*)&hq;
                float2 qp2 = __half22float2(hq);
                __half2 tfh = *(const __half2*)&TD[(size_t)t*DQ_ + cn];
                float2 tf2 = __half22float2(tfh);
                float te0 = time_emb[(size_t)ti*DQ_ + cn], te1 = time_emb[(size_t)ti*DQ_ + cn+1];
                *(__half2*)&PredIn[(size_t)t*KRO_ + DV_ + permc(cn)] =
                    __floats2half2_rn(fmaf(tf2.x, te0, qp2.x), fmaf(tf2.y, te1, qp2.y));
                acc[mi][ni][2*h] = 0.f; acc[mi][ni][2*h+1] = 0.f;
            }
        }
    }
    __syncthreads();

    auto stage2 = [&](int ch, int s) {
        uint32_t bb = bsb + s * 2048 * 4;
        cpa16(bb,           WMg + ch * 16);
        cpa16(bb + 64*16*4, WMg + (size_t)64*64 + ch * 16);
        asm volatile("cp.async.commit_group;");
    };
    stage2(0, 0); stage2(1, 1);
    #pragma unroll
    for (int ch = 0; ch < 4; ch++) {
        asm volatile("cp.async.wait_group 1;");
        __syncthreads();
        if (ch + 2 < 4) stage2(ch + 2, (ch + 2) % 3);
        else asm volatile("cp.async.commit_group;");
        const uint32_t* bs = Bs + (ch % 3) * 2048;
        uint4 alo[4], ahi[4];
        #pragma unroll
        for (int mi = 0; mi < 4; mi++) {
            alo[mi] = *(const uint4*)&Us[(wm0 + mi*16 + g)     * USTR + ch*16 + c*4];
            ahi[mi] = *(const uint4*)&Us[(wm0 + mi*16 + g + 8) * USTR + ch*16 + c*4];
        }
        #pragma unroll
        for (int ni = 0; ni < 4; ni++) {
            uint4 b = *(const uint4*)&bs[(wn0 + ni*8 + g) * 16 + c*4];
            #pragma unroll
            for (int mi = 0; mi < 4; mi++) {
                mma16(acc[mi][ni], alo[mi].x, ahi[mi].x, alo[mi].y, ahi[mi].y, b.x, b.y);
                mma16(acc[mi][ni], alo[mi].z, ahi[mi].z, alo[mi].w, ahi[mi].w, b.z, b.w);
            }
        }
    }

    float mx[4][2];
    #pragma unroll
    for (int mi = 0; mi < 4; mi++) { mx[mi][0] = -1e30f; mx[mi][1] = -1e30f; }
    #pragma unroll
    for (int ni = 0; ni < 4; ni++) {
        int cn = wn0 + ni*8 + c*2;
        bool ok0 = cn < M_, ok1 = (cn+1) < M_;
        #pragma unroll
        for (int mi = 0; mi < 4; mi++)
            #pragma unroll
            for (int h = 0; h < 2; h++) {
                if (ok0) mx[mi][h] = fmaxf(mx[mi][h], acc[mi][ni][2*h]);
                if (ok1) mx[mi][h] = fmaxf(mx[mi][h], acc[mi][ni][2*h+1]);
            }
    }
    #pragma unroll
    for (int mi = 0; mi < 4; mi++)
        #pragma unroll
        for (int h = 0; h < 2; h++) {
            mx[mi][h] = fmaxf(mx[mi][h], __shfl_xor_sync(0xffffffffu, mx[mi][h], 1));
            mx[mi][h] = fmaxf(mx[mi][h], __shfl_xor_sync(0xffffffffu, mx[mi][h], 2));
        }
    __syncthreads();
    if (c == 0) {
        #pragma unroll
        for (int mi = 0; mi < 4; mi++)
            #pragma unroll
            for (int h = 0; h < 2; h++)
                red[(w & 3) * 128 + wm0 + mi*16 + g + h*8] = mx[mi][h];
    }
    __syncthreads();
    float mxr[4][2];
    #pragma unroll
    for (int mi = 0; mi < 4; mi++)
        #pragma unroll
        for (int h = 0; h < 2; h++) {
            int r = wm0 + mi*16 + g + h*8;
            mxr[mi][h] = fmaxf(fmaxf(red[r], red[128 + r]), fmaxf(red[256 + r], red[384 + r]));
        }
    __syncthreads();
    float sum_[4][2];
    #pragma unroll
    for (int mi = 0; mi < 4; mi++) { sum_[mi][0] = 0.f; sum_[mi][1] = 0.f; }
    #pragma unroll
    for (int ni = 0; ni < 4; ni++) {
        int cn = wn0 + ni*8 + c*2;
        bool ok0 = cn < M_, ok1 = (cn+1) < M_;
        #pragma unroll
        for (int mi = 0; mi < 4; mi++)
            #pragma unroll
            for (int h = 0; h < 2; h++) {
                float e0 = ok0 ? __expf(acc[mi][ni][2*h]   - mxr[mi][h]) : 0.f;
                float e1 = ok1 ? __expf(acc[mi][ni][2*h+1] - mxr[mi][h]) : 0.f;
                acc[mi][ni][2*h] = e0; acc[mi][ni][2*h+1] = e1;
                sum_[mi][h] += e0 + e1;
            }
    }
    #pragma unroll
    for (int mi = 0; mi < 4; mi++)
        #pragma unroll
        for (int h = 0; h < 2; h++) {
            sum_[mi][h] += __shfl_xor_sync(0xffffffffu, sum_[mi][h], 1);
            sum_[mi][h] += __shfl_xor_sync(0xffffffffu, sum_[mi][h], 2);
        }
    if (c == 0) {
        #pragma unroll
        for (int mi = 0; mi < 4; mi++)
            #pragma unroll
            for (int h = 0; h < 2; h++)
                red[(w & 3) * 128 + wm0 + mi*16 + g + h*8] = sum_[mi][h];
    }
    __syncthreads();
    #pragma unroll
    for (int mi = 0; mi < 4; mi++) {
        #pragma unroll
        for (int h = 0; h < 2; h++) {
            int r = wm0 + mi*16 + g + h*8;
            float inv = 1.f / (red[r] + red[128 + r] + red[256 + r] + red[384 + r]);
            size_t t = m0 + r;
            #pragma unroll
            for (int ni = 0; ni < 4; ni++) {
                int cn = wn0 + ni*8 + c*2;
                if (cn < M_)   logits[t*LML_ + cn]   = acc[mi][ni][2*h]   * inv;
                if (cn+1 < M_) logits[t*LML_ + cn+1] = acc[mi][ni][2*h+1] * inv;
            }
        }
    }
}

// ==================== fused launches ====================
__global__ void __launch_bounds__(256, 2) k_fused1(
    const __half* A_lin, const __half* W1, const __half* W2,
    const float* b1, const float* b2,
    __half* TD, __half* X3,
    const int* q_data, const int* attempt_data,
    const int* hint_data, const int* hintTotal_data,
    const float* q_emb, const float* attempt_emb, const float* ht_emb,
    const __half* A_ea, const __half* Wea, const float* bea, __half* EA)
{
    extern __shared__ uint32_t sm[];
    int bx = blockIdx.x;
    if (bx < 2000) {
        dev_lin12(sm, bx * 128, A_lin, W1, W2, b1, b2, TD, X3,
                  q_data, attempt_data, hint_data, hintTotal_data,
                  q_emb, attempt_emb, ht_emb);
    } else {
        int idx = bx - 2000;
        dev_ea(sm, (idx % 1000) * 128, (idx / 1000) * 128, A_ea, Wea, bea, EA);
    }
}

__global__ void __launch_bounds__(256, 2) k_fused2(
    const __half* A_qp, const __half* W1, const __half* WM,
    const float* b1, const __half* TD,
    const int* time_data, const float* time_emb,
    __half* PredIn, float* logits,
    const __half* A_ea, const __half* Wea, const float* bea, __half* EA)
{
    extern __shared__ uint32_t sm[];
    int bx = blockIdx.x;
    if (bx < 1000) {
        dev_qplog(sm, bx * 128, A_qp, W1, WM, b1, TD, time_data, time_emb, PredIn, logits);
    } else {
        int idx = bx - 1000;
        dev_ea(sm, (idx % 1000) * 128, (2 + idx / 1000) * 128, A_ea, Wea, bea, EA);
    }
}

// ==================== readout GEMM ====================
__global__ void __launch_bounds__(256, 2) k_ro(
    const __half* __restrict__ A,
    const __half* __restrict__ W,
    const float* __restrict__ bias,
    const float* __restrict__ predW, float* __restrict__ predP)
{
    constexpr int NCH = 12, LDP = 192;
    extern __shared__ uint32_t sm[];
    uint32_t* As   = sm;
    uint32_t* Bs   = sm + 3 * 2048;
    float*    sred = (float*)(sm + 6 * 2048);

    const int tid  = threadIdx.x;
    const int m0   = blockIdx.y * 128;
    const int n0   = blockIdx.x * 128;
    const int lane = tid & 31, w = tid >> 5;
    const int g    = lane >> 2, c = lane & 3;
    const int wm0  = (w >> 2) * 64;
    const int wn0  = (w & 3) * 32;
    const int srow = tid >> 2;
    const int grp  = tid & 3;

    const uint32_t* Ag = (const uint32_t*)A + (size_t)(m0 + srow) * LDP + grp * 4;
    const uint32_t* Wg = (const uint32_t*)W + (size_t)(n0 + srow) * LDP + grp * 4;
    const uint32_t asb = (uint32_t)__cvta_generic_to_shared(As) + (srow * 16 + grp * 4) * 4;
    const uint32_t bsb = (uint32_t)__cvta_generic_to_shared(Bs) + (srow * 16 + grp * 4) * 4;

    float acc[4][4][4];
    #pragma unroll
    for (int i = 0; i < 4; i++)
        #pragma unroll
        for (int j = 0; j < 4; j++)
            #pragma unroll
            for (int r = 0; r < 4; r++) acc[i][j][r] = 0.f;

    auto stage = [&](int ch, int s) {
        uint32_t ab = asb + s * 2048 * 4;
        cpa16(ab,               Ag + ch * 16);
        cpa16(ab + 64 * 16 * 4, Ag + (size_t)64 * LDP + ch * 16);
        uint32_t bb = bsb + s * 2048 * 4;
        cpa16(bb,               Wg + ch * 16);
        cpa16(bb + 64 * 16 * 4, Wg + (size_t)64 * LDP + ch * 16);
        asm volatile("cp.async.commit_group;");
    };

    stage(0, 0); stage(1, 1);
    #pragma unroll
    for (int ch = 0; ch < NCH; ch++) {
        asm volatile("cp.async.wait_group 1;");
        __syncthreads();
        if (ch + 2 < NCH) stage(ch + 2, (ch + 2) % 3);
        else asm volatile("cp.async.commit_group;");
        const uint32_t* as = As + (ch % 3) * 2048;
        const uint32_t* bs = Bs + (ch % 3) * 2048;
        uint4 alo[4], ahi[4];
        #pragma unroll
        for (int mi = 0; mi < 4; mi++) {
            alo[mi] = *(const uint4*)&as[(wm0 + mi*16 + g)     * 16 + c*4];
            ahi[mi] = *(const uint4*)&as[(wm0 + mi*16 + g + 8) * 16 + c*4];
        }
        #pragma unroll
        for (int ni = 0; ni < 4; ni++) {
            uint4 b = *(const uint4*)&bs[(wn0 + ni*8 + g) * 16 + c*4];
            #pragma unroll
            for (int mi = 0; mi < 4; mi++) {
                mma16(acc[mi][ni], alo[mi].x, ahi[mi].x, alo[mi].y, ahi[mi].y, b.x, b.y);
                mma16(acc[mi][ni], alo[mi].z, ahi[mi].z, alo[mi].w, ahi[mi].w, b.z, b.w);
            }
        }
    }

    float rsum[4][2];
    #pragma unroll
    for (int mi = 0; mi < 4; mi++) { rsum[mi][0] = 0.f; rsum[mi][1] = 0.f; }
    #pragma unroll
    for (int ni = 0; ni < 4; ni++) {
        int cn = n0 + wn0 + ni*8 + c*2;
        float b0 = __ldg(&bias[cn]),  b1v = __ldg(&bias[cn+1]);
        float p0 = __ldg(&predW[cn]), p1 = __ldg(&predW[cn+1]);
        #pragma unroll
        for (int mi = 0; mi < 4; mi++) {
            rsum[mi][0] += ftanh(acc[mi][ni][0] + b0) * p0 + ftanh(acc[mi][ni][1] + b1v) * p1;
            rsum[mi][1] += ftanh(acc[mi][ni][2] + b0) * p0 + ftanh(acc[mi][ni][3] + b1v) * p1;
        }
    }
    __syncthreads();
    if (tid < 128) sred[tid] = 0.f;
    __syncthreads();
    #pragma unroll
    for (int mi = 0; mi < 4; mi++)
        #pragma unroll
        for (int h = 0; h < 2; h++) {
            float v = rsum[mi][h];
            v += __shfl_xor_sync(0xffffffffu, v, 1);
            v += __shfl_xor_sync(0xffffffffu, v, 2);
            if (c == 0) atomicAdd(&sred[wm0 + mi*16 + h*8 + g], v);
        }
    __syncthreads();
    if (tid < 128) predP[(size_t)blockIdx.x * T_ + m0 + tid] = sred[tid];
}

// ==================== small kernels ====================
__global__ void k_prep(const float* __restrict__ eW, const float* __restrict__ eb,
                       const float* __restrict__ aW, const float* __restrict__ ab,
                       const float* __restrict__ d1W, const float* __restrict__ d2W,
                       const float* __restrict__ roW, const float* __restrict__ Mk)
{
    int i = blockIdx.x * blockDim.x + threadIdx.x;
    int stride = gridDim.x * blockDim.x;
    for (int j = i; j < NEA_*KEA_; j += stride) {
        int n = j / KEA_, k = j % KEA_;
        g_Wea[n*KEA_ + ph(k)] = __float2half((n < DV_) ? eW[n*KEA_ + k] : aW[(n - DV_)*KEA_ + k]);
    }
    for (int j = i; j < DQ_*DQ_; j += stride) {
        int n = j / DQ_, k = j % DQ_;
        g_Wd1[n*DQ_ + ph(k)] = __float2half(d1W[j]);
        g_Wd2[n*DQ_ + ph(k)] = __float2half(d2W[j]);
    }
    for (int j = i; j < F_*KRO_; j += stride) {
        int n = j / KRO_, k = j % KRO_;
        g_Wro[n*KRO_ + ph(k)] = __float2half(roW[j]);
    }
    for (int j = i; j < 128*DQ_; j += stride) {
        int n = j / DQ_, k = j % DQ_;
        g_Wmk[n*DQ_ + ph(k)] = __float2half(n < M_ ? Mk[n*DQ_ + k] : 0.f);
    }
    for (int j = i; j < NEA_; j += stride) g_bea[j] = (j < DV_) ? eb[j] : ab[j - DV_];
    if (i < 2) g_accum[i] = 0.f;
}

__global__ void k_gather1(const int* __restrict__ q_data, const int* __restrict__ qa_data,
                          const int* __restrict__ time_data, const int* __restrict__ attempt_data,
                          const int* __restrict__ hint_data, const int* __restrict__ hintTotal_data,
                          const float* __restrict__ q_emb, const float* __restrict__ qa_emb,
                          const float* __restrict__ time_emb, const float* __restrict__ attempt_emb,
                          const float* __restrict__ ht_emb)
{
    int t = blockIdx.x, d = threadIdx.x;
    int pd = ph(d);
    int qi = q_data[t], ti = time_data[t], ai = attempt_data[t];
    int hi = hint_data[t], hti = hintTotal_data[t];
    float qe  = q_emb[(size_t)qi*DQ_ + d];
    float te  = time_emb[(size_t)ti*DQ_ + d];
    float ae  = attempt_emb[(size_t)ai*DQ_ + d];
    float he  = ht_emb[(size_t)hi*DQ_ + d];
    float hte = ht_emb[(size_t)hti*DQ_ + d];
    g_bufX[(size_t)t*DQ_ + pd]      = __float2half(te + qe);
    g_bufX[(size_t)(T_+t)*DQ_ + pd] = __float2half(he + hte + ae + qe);
    int qai = qa_data[t];
    g_bufQA[(size_t)t*DV_ + pd]          = __float2half(qa_emb[(size_t)qai*DV_ + d]);
    g_bufQA[(size_t)t*DV_ + ph(d + DQ_)] = __float2half(qa_emb[(size_t)qai*DV_ + DQ_ + d]);
}

// Scan: DV split 2-way AND m split 2-way across lane pairs.
// 256 threads: tid = dl*2 + mh. mh0 owns m[0,26), mh1 owns m[26,50)+zero pad.
// rd combined via shfl_xor(1). Zero-pad slots ws[..][50..51]=0 make both
// halves a fixed 13-pair f32x2 loop (w=0 pair: mv unchanged, rd += 0).
__global__ void __launch_bounds__(256) k_scan(const float* __restrict__ Mv0)
{
    int b   = blockIdx.x;
    int tid = threadIdx.x;
    int lane = tid & 31;
    int wid  = tid >> 5;          // 0..7
    int mh  = tid & 1;
    int dl  = tid >> 1;           // 0..127
    int d   = blockIdx.y * 128 + dl;
    int pe  = ph(d);
    int pa  = ph(d + DV_);
    const int moff = mh ? 26 : 0;

    unsigned long long mv2[13];
    #pragma unroll
    for (int j = 0; j < 13; j++) {
        int ma = moff + 2*j, mb = moff + 2*j + 1;
        if (ma > M_-1) ma = M_-1;
        if (mb > M_-1) mb = M_-1;
        mv2[j] = pk2(Mv0[ma*DV_ + d], Mv0[mb*DV_ + d]);
    }

    __shared__ float ws[8][2][56];
    size_t t0 = (size_t)b * S_;
    // zero the pad slots once (never overwritten: fills only touch idx<50)
    if (lane < 2) { ws[wid][0][50 + lane] = 0.f; ws[wid][1][50 + lane] = 0.f; }
    if (lane < M_)      ws[wid][0][lane]      = g_logits[t0*LML_ + lane];
    if (lane + 32 < M_) ws[wid][0][lane + 32] = g_logits[t0*LML_ + lane + 32];
    float e = __half2float(g_bufEA[t0*NEA_ + pe]);
    float a = __half2float(g_bufEA[t0*NEA_ + pa]);
    __syncwarp();

    for (int s = 0; s < S_; s++) {
        size_t t = t0 + s;
        float en = 0.f, an = 0.f;
        if (s + 1 < S_) {
            en = __half2float(g_bufEA[(t+1)*NEA_ + pe]);
            an = __half2float(g_bufEA[(t+1)*NEA_ + pa]);
            int nb = (s+1) & 1;
            if (lane < M_)      ws[wid][nb][lane]      = g_logits[(t+1)*LML_ + lane];
            if (lane + 32 < M_) ws[wid][nb][lane + 32] = g_logits[(t+1)*LML_ + lane + 32];
        }
        const float* wcur = ws[wid][s & 1];
        unsigned long long ne2 = pk2(-e, -e);
        unsigned long long a2  = pk2(a, a);
        unsigned long long rd2 = 0ull;
        #pragma unroll
        for (int j = 0; j < 13; j++) {
            float2 wp = *(const float2*)&wcur[moff + 2*j];
            unsigned long long w2 = pk2(wp.x, wp.y);
            rd2 = fma2(w2, mv2[j], rd2);
            mv2[j] = fma2(w2, fma2(ne2, mv2[j], a2), mv2[j]);
        }
        float2 rd = upk2(rd2);
        float r = rd.x + rd.y;
        r += __shfl_xor_sync(0xffffffffu, r, 1);
        if (mh == 0) g_PredIn[t*KRO_ + pe] = __float2half(r);
        __syncwarp();
        e = en; a = an;
    }
}

__global__ void k_loss(const int* __restrict__ target, const float* __restrict__ pred_b,
                       float* __restrict__ out)
{
    int i = blockIdx.x * blockDim.x + threadIdx.x;
    float le = 0.f, cnt = 0.f;
    if (i < T_) {
        float p = g_predP[0][i] + g_predP[1][i] + g_predP[2][i] + g_predP[3][i] + pred_b[0];
        int tg = target[i];
        bool mask = tg >= 1;
        float y = mask ? (float)(tg - 1) : 0.f;
        float sig = 1.f / (1.f + expf(-p));
        out[1 + i]      = mask ? sig : 0.f;
        out[1 + T_ + i] = mask ? y   : 0.f;
        if (mask) {
            le = fmaxf(p, 0.f) + log1pf(expf(-fabsf(p))) - p * y;
            cnt = 1.f;
        }
    }
    __shared__ float sle[256], scn[256];
    sle[threadIdx.x] = le; scn[threadIdx.x] = cnt;
    __syncthreads();
    for (int o = 128; o; o >>= 1) {
        if (threadIdx.x < o) { sle[threadIdx.x] += sle[threadIdx.x + o]; scn[threadIdx.x] += scn[threadIdx.x + o]; }
        __syncthreads();
    }
    if (threadIdx.x == 0) { atomicAdd(&g_accum[0], sle[0]); atomicAdd(&g_accum[1], scn[0]); }
}

__global__ void k_final(float* __restrict__ out)
{
    out[0] = g_accum[0] / fmaxf(g_accum[1], 1.f);
}

// ==================== host ====================
extern "C" void kernel_launch(void* const* d_in, const int* in_sizes, int n_in,
                              void* d_out, int out_size)
{
    const int*   q_data      = (const int*)  d_in[0];
    const int*   qa_data     = (const int*)  d_in[1];
    const int*   target      = (const int*)  d_in[2];
    const int*   time_data   = (const int*)  d_in[3];
    const int*   attempt_data= (const int*)  d_in[4];
    const int*   hint_data   = (const int*)  d_in[5];
    const int*   hintTotal   = (const int*)  d_in[6];
    const float* q_emb       = (const float*)d_in[7];
    const float* qa_emb      = (const float*)d_in[8];
    const float* time_emb    = (const float*)d_in[9];
    const float* attempt_emb = (const float*)d_in[10];
    const float* ht_emb      = (const float*)d_in[11];
    const float* Mk          = (const float*)d_in[12];
    const float* Mv0         = (const float*)d_in[13];
    const float* diff_W      = (const float*)d_in[14];
    const float* diff_b      = (const float*)d_in[15];
    const float* diff2_W     = (const float*)d_in[16];
    const float* diff2_b     = (const float*)d_in[17];
    const float* erase_W     = (const float*)d_in[18];
    const float* erase_b     = (const float*)d_in[19];
    const float* add_W       = (const float*)d_in[20];
    const float* add_b       = (const float*)d_in[21];
    const float* read_W      = (const float*)d_in[22];
    const float* read_b      = (const float*)d_in[23];
    const float* pred_W      = (const float*)d_in[24];
    const float* pred_b      = (const float*)d_in[25];
    float* out = (float*)d_out;

    __half *bufX, *bufX3, *bufTD, *bufQA, *bufEA, *predin;
    __half *Wea, *Wd1, *Wd2, *Wro, *Wmk;
    float *logits, *predP, *bea;
    cudaGetSymbolAddress((void**)&bufX,   g_bufX);
    cudaGetSymbolAddress((void**)&bufX3,  g_bufX3);
    cudaGetSymbolAddress((void**)&bufTD,  g_bufTD);
    cudaGetSymbolAddress((void**)&bufQA,  g_bufQA);
    cudaGetSymbolAddress((void**)&bufEA,  g_bufEA);
    cudaGetSymbolAddress((void**)&predin, g_PredIn);
    cudaGetSymbolAddress((void**)&logits, g_logits);
    cudaGetSymbolAddress((void**)&predP,  g_predP);
    cudaGetSymbolAddress((void**)&Wea,    g_Wea);
    cudaGetSymbolAddress((void**)&Wd1,    g_Wd1);
    cudaGetSymbolAddress((void**)&Wd2,    g_Wd2);
    cudaGetSymbolAddress((void**)&Wro,    g_Wro);
    cudaGetSymbolAddress((void**)&Wmk,    g_Wmk);
    cudaGetSymbolAddress((void**)&bea,    g_bea);

    const int SMG = (6*2048 + 128) * 4;
    const int SML = (6*2048 + 128*USTR) * 4;
    const int SMQ = (6*2048 + 128*USTR + 512) * 4;
    cudaFuncSetAttribute(k_fused1, cudaFuncAttributeMaxDynamicSharedMemorySize, SML);
    cudaFuncSetAttribute(k_fused2, cudaFuncAttributeMaxDynamicSharedMemorySize, SMQ);
    cudaFuncSetAttribute(k_ro,     cudaFuncAttributeMaxDynamicSharedMemorySize, SMG);

    k_prep<<<1024, 256>>>(erase_W, erase_b, add_W, add_b, diff_W, diff2_W, read_W, Mk);
    k_gather1<<<T_, 128>>>(q_data, qa_data, time_data, attempt_data, hint_data, hintTotal,
                           q_emb, qa_emb, time_emb, attempt_emb, ht_emb);
    k_fused1<<<4000, 256, SML>>>(bufX, Wd1, Wd2, diff_b, diff2_b, bufTD, bufX3,
                                 q_data, attempt_data, hint_data, hintTotal,
                                 q_emb, attempt_emb, ht_emb,
                                 bufQA, Wea, bea, bufEA);
    k_fused2<<<3000, 256, SMQ>>>(bufX3, Wd1, Wmk, diff_b, bufTD,
                                 time_data, time_emb, predin, logits,
                                 bufQA, Wea, bea, bufEA);
    k_scan<<<dim3(B_, 2), 256>>>(Mv0);
    k_ro<<<dim3(4, 1000), 256, SMG>>>(predin, Wro, read_b, pred_W, predP);
    k_loss<<<(T_ + 255)/256, 256>>>(target, pred_b, out);
    k_final<<<1, 1>>>(out);
}

// round 15
// speedup vs baseline: 1.1233x; 1.1233x over previous
#include <cuda_runtime.h>
#include <cuda_fp16.h>
#include <math.h>
#include <stdint.h>

#define B_   256
#define S_   500
#define T_   (B_*S_)        // 128000
#define DQ_  128
#define DV_  256
#define M_   50
#define F_   512
#define NEA_ 512
#define KEA_ 256
#define KRO_ 384
#define LML_ 64
#define USTR 80

// ---------------- scratch (device globals) ----------------
__device__ __half g_bufX [2*T_*DQ_];
__device__ __half g_bufX3[T_*DQ_];
__device__ __half g_bufTD[T_*DQ_];
__device__ __half g_bufQA[T_*DV_];
__device__ __half g_bufEA[T_*NEA_];
__device__ __half g_PredIn[T_*KRO_];
__device__ float  g_logits[T_*LML_];
__device__ float  g_predP[4][T_];
__device__ float  g_accum[2];
__device__ __half g_Wea[NEA_*KEA_];
__device__ __half g_Wd1[DQ_*DQ_];
__device__ __half g_Wd2[DQ_*DQ_];
__device__ __half g_Wro[F_*KRO_];
__device__ __half g_Wmk[128*DQ_];
__device__ float  g_bea[NEA_];

// ==================== helpers ====================
__device__ __forceinline__ int ph(int d) {
    int pair = d >> 1;
    int pi   = pair & 15;
    int pp   = (pair & ~15) | ((pi & 3) * 4 + (pi >> 2));
    return pp * 2 + (d & 1);
}
__device__ __forceinline__ int permc(int cn) {
    int pair = cn >> 1;
    int pi   = pair & 15;
    int pp   = (pair & ~15) | ((pi & 3) * 4 + (pi >> 2));
    return pp * 2;
}
__device__ __forceinline__ float fsig(float x) { return 1.f / (1.f + __expf(-x)); }
__device__ __forceinline__ float ftanh(float x) {
    float ax = fabsf(x);
    float t  = 1.f - 2.f / (1.f + __expf(2.f * ax));
    return copysignf(t, x);
}
__device__ __forceinline__ void mma16(float* d,
    uint32_t a0, uint32_t a1, uint32_t a2, uint32_t a3,
    uint32_t b0, uint32_t b1)
{
    asm volatile(
        "mma.sync.aligned.m16n8k16.row.col.f32.f16.f16.f32 "
        "{%0,%1,%2,%3},{%4,%5,%6,%7},{%8,%9},{%0,%1,%2,%3};"
        : "+f"(d[0]), "+f"(d[1]), "+f"(d[2]), "+f"(d[3])
        : "r"(a0), "r"(a1), "r"(a2), "r"(a3), "r"(b0), "r"(b1));
}
__device__ __forceinline__ void cpa16(uint32_t dst, const void* src) {
    asm volatile("cp.async.cg.shared.global [%0], [%1], 16;" :: "r"(dst), "l"(src));
}
// packed f32x2
__device__ __forceinline__ unsigned long long pk2(float lo, float hi) {
    unsigned long long r;
    asm("mov.b64 %0, {%1, %2};" : "=l"(r) : "f"(lo), "f"(hi));
    return r;
}
__device__ __forceinline__ float2 upk2(unsigned long long v) {
    float2 r;
    asm("mov.b64 {%0, %1}, %2;" : "=f"(r.x), "=f"(r.y) : "l"(v));
    return r;
}
__device__ __forceinline__ unsigned long long fma2(
    unsigned long long a, unsigned long long b, unsigned long long c)
{
    unsigned long long d;
    asm("fma.rn.f32x2 %0, %1, %2, %3;" : "=l"(d) : "l"(a), "l"(b), "l"(c));
    return d;
}

// ==================== device GEMM body: EA (K=256, perm store) ==============
__device__ __forceinline__ void dev_ea(uint32_t* sm, int m0, int n0,
    const __half* __restrict__ A, const __half* __restrict__ W,
    const float* __restrict__ bias, __half* __restrict__ C)
{
    constexpr int NCH = 8, LDP = 128;
    uint32_t* As = sm;
    uint32_t* Bs = sm + 3 * 2048;

    const int tid  = threadIdx.x;
    const int lane = tid & 31, w = tid >> 5;
    const int g    = lane >> 2, c = lane & 3;
    const int wm0  = (w >> 2) * 64;
    const int wn0  = (w & 3) * 32;
    const int srow = tid >> 2;
    const int grp  = tid & 3;

    const uint32_t* Ag = (const uint32_t*)A + (size_t)(m0 + srow) * LDP + grp * 4;
    const uint32_t* Wg = (const uint32_t*)W + (size_t)(n0 + srow) * LDP + grp * 4;
    const uint32_t asb = (uint32_t)__cvta_generic_to_shared(As) + (srow * 16 + grp * 4) * 4;
    const uint32_t bsb = (uint32_t)__cvta_generic_to_shared(Bs) + (srow * 16 + grp * 4) * 4;

    float acc[4][4][4];
    #pragma unroll
    for (int i = 0; i < 4; i++)
        #pragma unroll
        for (int j = 0; j < 4; j++)
            #pragma unroll
            for (int r = 0; r < 4; r++) acc[i][j][r] = 0.f;

    auto stage = [&](int ch, int s) {
        uint32_t ab = asb + s * 2048 * 4;
        cpa16(ab,               Ag + ch * 16);
        cpa16(ab + 64 * 16 * 4, Ag + (size_t)64 * LDP + ch * 16);
        uint32_t bb = bsb + s * 2048 * 4;
        cpa16(bb,               Wg + ch * 16);
        cpa16(bb + 64 * 16 * 4, Wg + (size_t)64 * LDP + ch * 16);
        asm volatile("cp.async.commit_group;");
    };

    stage(0, 0); stage(1, 1);
    #pragma unroll
    for (int ch = 0; ch < NCH; ch++) {
        asm volatile("cp.async.wait_group 1;");
        __syncthreads();
        if (ch + 2 < NCH) stage(ch + 2, (ch + 2) % 3);
        else asm volatile("cp.async.commit_group;");
        const uint32_t* as = As + (ch % 3) * 2048;
        const uint32_t* bs = Bs + (ch % 3) * 2048;
        uint4 alo[4], ahi[4];
        #pragma unroll
        for (int mi = 0; mi < 4; mi++) {
            alo[mi] = *(const uint4*)&as[(wm0 + mi*16 + g)     * 16 + c*4];
            ahi[mi] = *(const uint4*)&as[(wm0 + mi*16 + g + 8) * 16 + c*4];
        }
        #pragma unroll
        for (int ni = 0; ni < 4; ni++) {
            uint4 b = *(const uint4*)&bs[(wn0 + ni*8 + g) * 16 + c*4];
            #pragma unroll
            for (int mi = 0; mi < 4; mi++) {
                mma16(acc[mi][ni], alo[mi].x, ahi[mi].x, alo[mi].y, ahi[mi].y, b.x, b.y);
                mma16(acc[mi][ni], alo[mi].z, ahi[mi].z, alo[mi].w, ahi[mi].w, b.z, b.w);
            }
        }
    }

    #pragma unroll
    for (int ni = 0; ni < 4; ni++) {
        int cn  = n0 + wn0 + ni*8 + c*2;
        int cnp = permc(cn);
        float b0 = __ldg(&bias[cn]), b1 = __ldg(&bias[cn+1]);
        #pragma unroll
        for (int mi = 0; mi < 4; mi++) {
            int r0 = m0 + wm0 + mi*16 + g;
            float v0 = acc[mi][ni][0] + b0, v1 = acc[mi][ni][1] + b1;
            float v2 = acc[mi][ni][2] + b0, v3 = acc[mi][ni][3] + b1;
            if (cn < DV_) { v0 = fsig(v0); v1 = fsig(v1); v2 = fsig(v2); v3 = fsig(v3); }
            else          { v0 = ftanh(v0); v1 = ftanh(v1); v2 = ftanh(v2); v3 = ftanh(v3); }
            *(__half2*)&C[(size_t)r0    *NEA_ + cnp] = __floats2half2_rn(v0, v1);
            *(__half2*)&C[(size_t)(r0+8)*NEA_ + cnp] = __floats2half2_rn(v2, v3);
        }
    }
}

// ==================== device body: lin12 ====================
__device__ __forceinline__ void dev_lin12(uint32_t* sm, int m0,
    const __half* __restrict__ A,
    const __half* __restrict__ W1, const __half* __restrict__ W2,
    const float* __restrict__ b1, const float* __restrict__ b2,
    __half* __restrict__ TD, __half* __restrict__ X3,
    const int* __restrict__ q_data, const int* __restrict__ attempt_data,
    const int* __restrict__ hint_data, const int* __restrict__ hintTotal_data,
    const float* __restrict__ q_emb, const float* __restrict__ attempt_emb,
    const float* __restrict__ ht_emb)
{
    uint32_t* Xs = sm;
    uint32_t* Bs = sm + 3*2048;
    uint32_t* Us = sm + 6*2048;

    const int tid  = threadIdx.x;
    const int lane = tid & 31, w = tid >> 5;
    const int g    = lane >> 2, c = lane & 3;
    const int wm0  = (w >> 2) * 64;
    const int wn0  = (w & 3) * 32;
    const int srow = tid >> 2;
    const int grp  = tid & 3;

    const uint32_t* Ag  = (const uint32_t*)A  + (size_t)(m0 + srow) * 64 + grp * 4;
    const uint32_t* W1g = (const uint32_t*)W1 + (size_t)srow * 64 + grp * 4;
    const uint32_t* W2g = (const uint32_t*)W2 + (size_t)srow * 64 + grp * 4;

    const uint32_t xsb = (uint32_t)__cvta_generic_to_shared(Xs) + (srow*16 + grp*4) * 4;
    const uint32_t bsb = (uint32_t)__cvta_generic_to_shared(Bs) + (srow*16 + grp*4) * 4;

    float acc[4][4][4];
    #pragma unroll
    for (int i = 0; i < 4; i++)
        #pragma unroll
        for (int j = 0; j < 4; j++)
            #pragma unroll
            for (int r = 0; r < 4; r++) acc[i][j][r] = 0.f;

    auto stage1 = [&](int ch, int s) {
        uint32_t xb = xsb + s * 2048 * 4;
        cpa16(xb,           Ag + ch * 16);
        cpa16(xb + 64*16*4, Ag + (size_t)64*64 + ch * 16);
        uint32_t bb = bsb + s * 2048 * 4;
        cpa16(bb,           W1g + ch * 16);
        cpa16(bb + 64*16*4, W1g + (size_t)64*64 + ch * 16);
        asm volatile("cp.async.commit_group;");
    };

    stage1(0, 0); stage1(1, 1);
    #pragma unroll
    for (int ch = 0; ch < 4; ch++) {
        asm volatile("cp.async.wait_group 1;");
        __syncthreads();
        if (ch + 2 < 4) stage1(ch + 2, (ch + 2) % 3);
        else asm volatile("cp.async.commit_group;");
        const uint32_t* xs = Xs + (ch % 3) * 2048;
        const uint32_t* bs = Bs + (ch % 3) * 2048;
        uint4 alo[4], ahi[4];
        #pragma unroll
        for (int mi = 0; mi < 4; mi++) {
            alo[mi] = *(const uint4*)&xs[(wm0 + mi*16 + g)     * 16 + c*4];
            ahi[mi] = *(const uint4*)&xs[(wm0 + mi*16 + g + 8) * 16 + c*4];
        }
        #pragma unroll
        for (int ni = 0; ni < 4; ni++) {
            uint4 b = *(const uint4*)&bs[(wn0 + ni*8 + g) * 16 + c*4];
            #pragma unroll
            for (int mi = 0; mi < 4; mi++) {
                mma16(acc[mi][ni], alo[mi].x, ahi[mi].x, alo[mi].y, ahi[mi].y, b.x, b.y);
                mma16(acc[mi][ni], alo[mi].z, ahi[mi].z, alo[mi].w, ahi[mi].w, b.z, b.w);
            }
        }
    }
    asm volatile("cp.async.wait_group 0;");

    #pragma unroll
    for (int ni = 0; ni < 4; ni++) {
        int cn = wn0 + ni*8 + c*2;
        float bb0 = __ldg(&b1[cn]), bb1 = __ldg(&b1[cn+1]);
        int pw = permc(cn) >> 1;
        #pragma unroll
        for (int mi = 0; mi < 4; mi++) {
            int r0 = wm0 + mi*16 + g;
            __half2 h0 = __floats2half2_rn(ftanh(acc[mi][ni][0] + bb0), ftanh(acc[mi][ni][1] + bb1));
            __half2 h1 = __floats2half2_rn(ftanh(acc[mi][ni][2] + bb0), ftanh(acc[mi][ni][3] + bb1));
            Us[r0*USTR + pw]     = *(uint32_t*)&h0;
            Us[(r0+8)*USTR + pw] = *(uint32_t*)&h1;
            acc[mi][ni][0] = acc[mi][ni][1] = acc[mi][ni][2] = acc[mi][ni][3] = 0.f;
        }
    }
    __syncthreads();

    auto stage2 = [&](int ch, int s) {
        uint32_t bb = bsb + s * 2048 * 4;
        cpa16(bb,           W2g + ch * 16);
        cpa16(bb + 64*16*4, W2g + (size_t)64*64 + ch * 16);
        asm volatile("cp.async.commit_group;");
    };
    stage2(0, 0); stage2(1, 1);
    #pragma unroll
    for (int ch = 0; ch < 4; ch++) {
        asm volatile("cp.async.wait_group 1;");
        __syncthreads();
        if (ch + 2 < 4) stage2(ch + 2, (ch + 2) % 3);
        else asm volatile("cp.async.commit_group;");
        const uint32_t* bs = Bs + (ch % 3) * 2048;
        uint4 alo[4], ahi[4];
        #pragma unroll
        for (int mi = 0; mi < 4; mi++) {
            alo[mi] = *(const uint4*)&Us[(wm0 + mi*16 + g)     * USTR + ch*16 + c*4];
            ahi[mi] = *(const uint4*)&Us[(wm0 + mi*16 + g + 8) * USTR + ch*16 + c*4];
        }
        #pragma unroll
        for (int ni = 0; ni < 4; ni++) {
            uint4 b = *(const uint4*)&bs[(wn0 + ni*8 + g) * 16 + c*4];
            #pragma unroll
            for (int mi = 0; mi < 4; mi++) {
                mma16(acc[mi][ni], alo[mi].x, ahi[mi].x, alo[mi].y, ahi[mi].y, b.x, b.y);
                mma16(acc[mi][ni], alo[mi].z, ahi[mi].z, alo[mi].w, ahi[mi].w, b.z, b.w);
            }
        }
    }

    const bool isdiff = (m0 >= T_);
    #pragma unroll
    for (int mi = 0; mi < 4; mi++) {
        #pragma unroll
        for (int h = 0; h < 2; h++) {
            int r = wm0 + mi*16 + g + h*8;
            int t = m0 + r;
            if (!isdiff) {
                #pragma unroll
                for (int ni = 0; ni < 4; ni++) {
                    int cn = wn0 + ni*8 + c*2;
                    float v0 = fsig(acc[mi][ni][2*h]   + __ldg(&b2[cn]));
                    float v1 = fsig(acc[mi][ni][2*h+1] + __ldg(&b2[cn+1]));
                    *(__half2*)&TD[(size_t)t*DQ_ + cn] = __floats2half2_rn(v0, v1);
                }
            } else {
                int tt = t - T_;
                int qi = q_data[tt], ai = attempt_data[tt];
                int hi = hint_data[tt], hti = hintTotal_data[tt];
                #pragma unroll
                for (int ni = 0; ni < 4; ni++) {
                    int cn = wn0 + ni*8 + c*2;
                    float v0 = fsig(acc[mi][ni][2*h]   + __ldg(&b2[cn]));
                    float v1 = fsig(acc[mi][ni][2*h+1] + __ldg(&b2[cn+1]));
                    float qe0 = q_emb[(size_t)qi*DQ_ + cn],   qe1 = q_emb[(size_t)qi*DQ_ + cn+1];
                    float g0  = attempt_emb[(size_t)ai*DQ_ + cn]
                              + ht_emb[(size_t)hi*DQ_ + cn] + ht_emb[(size_t)hti*DQ_ + cn];
                    float g1  = attempt_emb[(size_t)ai*DQ_ + cn+1]
                              + ht_emb[(size_t)hi*DQ_ + cn+1] + ht_emb[(size_t)hti*DQ_ + cn+1];
                    *(__half2*)&X3[(size_t)tt*DQ_ + permc(cn)] =
                        __floats2half2_rn(fmaf(v0, g0, qe0), fmaf(v1, g1, qe1));
                }
            }
        }
    }
}

// ==================== device body: qplog ====================
__device__ __forceinline__ void dev_qplog(uint32_t* sm, int m0,
    const __half* __restrict__ A,
    const __half* __restrict__ W1, const __half* __restrict__ WM,
    const float* __restrict__ b1, const __half* __restrict__ TD,
    const int* __restrict__ time_data, const float* __restrict__ time_emb,
    __half* __restrict__ PredIn, float* __restrict__ logits)
{
    uint32_t* Xs  = sm;
    uint32_t* Bs  = sm + 3*2048;
    uint32_t* Us  = sm + 6*2048;
    float*    red = (float*)(sm + 6*2048 + 128*USTR);

    const int tid  = threadIdx.x;
    const int lane = tid & 31, w = tid >> 5;
    const int g    = lane >> 2, c = lane & 3;
    const int wm0  = (w >> 2) * 64;
    const int wn0  = (w & 3) * 32;
    const int srow = tid >> 2;
    const int grp  = tid & 3;

    const uint32_t* Ag  = (const uint32_t*)A  + (size_t)(m0 + srow) * 64 + grp * 4;
    const uint32_t* W1g = (const uint32_t*)W1 + (size_t)srow * 64 + grp * 4;
    const uint32_t* WMg = (const uint32_t*)WM + (size_t)srow * 64 + grp * 4;

    const uint32_t xsb = (uint32_t)__cvta_generic_to_shared(Xs) + (srow*16 + grp*4) * 4;
    const uint32_t bsb = (uint32_t)__cvta_generic_to_shared(Bs) + (srow*16 + grp*4) * 4;

    float acc[4][4][4];
    #pragma unroll
    for (int i = 0; i < 4; i++)
        #pragma unroll
        for (int j = 0; j < 4; j++)
            #pragma unroll
            for (int r = 0; r < 4; r++) acc[i][j][r] = 0.f;

    auto stage1 = [&](int ch, int s) {
        uint32_t xb = xsb + s * 2048 * 4;
        cpa16(xb,           Ag + ch * 16);
        cpa16(xb + 64*16*4, Ag + (size_t)64*64 + ch * 16);
        uint32_t bb = bsb + s * 2048 * 4;
        cpa16(bb,           W1g + ch * 16);
        cpa16(bb + 64*16*4, W1g + (size_t)64*64 + ch * 16);
        asm volatile("cp.async.commit_group;");
    };
    stage1(0, 0); stage1(1, 1);
    #pragma unroll
    for (int ch = 0; ch < 4; ch++) {
        asm volatile("cp.async.wait_group 1;");
        __syncthreads();
        if (ch + 2 < 4) stage1(ch + 2, (ch + 2) % 3);
        else asm volatile("cp.async.commit_group;");
        const uint32_t* xs = Xs + (ch % 3) * 2048;
        const uint32_t* bs = Bs + (ch % 3) * 2048;
        uint4 alo[4], ahi[4];
        #pragma unroll
        for (int mi = 0; mi < 4; mi++) {
            alo[mi] = *(const uint4*)&xs[(wm0 + mi*16 + g)     * 16 + c*4];
            ahi[mi] = *(const uint4*)&xs[(wm0 + mi*16 + g + 8) * 16 + c*4];
        }
        #pragma unroll
        for (int ni = 0; ni < 4; ni++) {
            uint4 b = *(const uint4*)&bs[(wn0 + ni*8 + g) * 16 + c*4];
            #pragma unroll
            for (int mi = 0; mi < 4; mi++) {
                mma16(acc[mi][ni], alo[mi].x, ahi[mi].x, alo[mi].y, ahi[mi].y, b.x, b.y);
                mma16(acc[mi][ni], alo[mi].z, ahi[mi].z, alo[mi].w, ahi[mi].w, b.z, b.w);
            }
        }
    }
    asm volatile("cp.async.wait_group 0;");

    #pragma unroll
    for (int mi = 0; mi < 4; mi++) {
        #pragma unroll
        for (int h = 0; h < 2; h++) {
            int r = wm0 + mi*16 + g + h*8;
            int t = m0 + r;
            int ti = time_data[t];
            #pragma unroll
            for (int ni = 0; ni < 4; ni++) {
                int cn = wn0 + ni*8 + c*2;
                float q0 = acc[mi][ni][2*h]   + __ldg(&b1[cn]);
                float q1 = acc[mi][ni][2*h+1] + __ldg(&b1[cn+1]);
                __half2 hq = __floats2half2_rn(q0, q1);
                Us[r*USTR + (permc(cn) >> 1)] = *(uint32_t*)&hq;
                float2 qp2 = __half22float2(hq);
                __half2 tfh = *(const __half2*)&TD[(size_t)t*DQ_ + cn];
                float2 tf2 = __half22float2(tfh);
                float te0 = time_emb[(size_t)ti*DQ_ + cn], te1 = time_emb[(size_t)ti*DQ_ + cn+1];
                *(__half2*)&PredIn[(size_t)t*KRO_ + DV_ + permc(cn)] =
                    __floats2half2_rn(fmaf(tf2.x, te0, qp2.x), fmaf(tf2.y, te1, qp2.y));
                acc[mi][ni][2*h] = 0.f; acc[mi][ni][2*h+1] = 0.f;
            }
        }
    }
    __syncthreads();

    auto stage2 = [&](int ch, int s) {
        uint32_t bb = bsb + s * 2048 * 4;
        cpa16(bb,           WMg + ch * 16);
        cpa16(bb + 64*16*4, WMg + (size_t)64*64 + ch * 16);
        asm volatile("cp.async.commit_group;");
    };
    stage2(0, 0); stage2(1, 1);
    #pragma unroll
    for (int ch = 0; ch < 4; ch++) {
        asm volatile("cp.async.wait_group 1;");
        __syncthreads();
        if (ch + 2 < 4) stage2(ch + 2, (ch + 2) % 3);
        else asm volatile("cp.async.commit_group;");
        const uint32_t* bs = Bs + (ch % 3) * 2048;
        uint4 alo[4], ahi[4];
        #pragma unroll
        for (int mi = 0; mi < 4; mi++) {
            alo[mi] = *(const uint4*)&Us[(wm0 + mi*16 + g)     * USTR + ch*16 + c*4];
            ahi[mi] = *(const uint4*)&Us[(wm0 + mi*16 + g + 8) * USTR + ch*16 + c*4];
        }
        #pragma unroll
        for (int ni = 0; ni < 4; ni++) {
            uint4 b = *(const uint4*)&bs[(wn0 + ni*8 + g) * 16 + c*4];
            #pragma unroll
            for (int mi = 0; mi < 4; mi++) {
                mma16(acc[mi][ni], alo[mi].x, ahi[mi].x, alo[mi].y, ahi[mi].y, b.x, b.y);
                mma16(acc[mi][ni], alo[mi].z, ahi[mi].z, alo[mi].w, ahi[mi].w, b.z, b.w);
            }
        }
    }

    float mx[4][2];
    #pragma unroll
    for (int mi = 0; mi < 4; mi++) { mx[mi][0] = -1e30f; mx[mi][1] = -1e30f; }
    #pragma unroll
    for (int ni = 0; ni < 4; ni++) {
        int cn = wn0 + ni*8 + c*2;
        bool ok0 = cn < M_, ok1 = (cn+1) < M_;
        #pragma unroll
        for (int mi = 0; mi < 4; mi++)
            #pragma unroll
            for (int h = 0; h < 2; h++) {
                if (ok0) mx[mi][h] = fmaxf(mx[mi][h], acc[mi][ni][2*h]);
                if (ok1) mx[mi][h] = fmaxf(mx[mi][h], acc[mi][ni][2*h+1]);
            }
    }
    #pragma unroll
    for (int mi = 0; mi < 4; mi++)
        #pragma unroll
        for (int h = 0; h < 2; h++) {
            mx[mi][h] = fmaxf(mx[mi][h], __shfl_xor_sync(0xffffffffu, mx[mi][h], 1));
            mx[mi][h] = fmaxf(mx[mi][h], __shfl_xor_sync(0xffffffffu, mx[mi][h], 2));
        }
    __syncthreads();
    if (c == 0) {
        #pragma unroll
        for (int mi = 0; mi < 4; mi++)
            #pragma unroll
            for (int h = 0; h < 2; h++)
                red[(w & 3) * 128 + wm0 + mi*16 + g + h*8] = mx[mi][h];
    }
    __syncthreads();
    float mxr[4][2];
    #pragma unroll
    for (int mi = 0; mi < 4; mi++)
        #pragma unroll
        for (int h = 0; h < 2; h++) {
            int r = wm0 + mi*16 + g + h*8;
            mxr[mi][h] = fmaxf(fmaxf(red[r], red[128 + r]), fmaxf(red[256 + r], red[384 + r]));
        }
    __syncthreads();
    float sum_[4][2];
    #pragma unroll
    for (int mi = 0; mi < 4; mi++) { sum_[mi][0] = 0.f; sum_[mi][1] = 0.f; }
    #pragma unroll
    for (int ni = 0; ni < 4; ni++) {
        int cn = wn0 + ni*8 + c*2;
        bool ok0 = cn < M_, ok1 = (cn+1) < M_;
        #pragma unroll
        for (int mi = 0; mi < 4; mi++)
            #pragma unroll
            for (int h = 0; h < 2; h++) {
                float e0 = ok0 ? __expf(acc[mi][ni][2*h]   - mxr[mi][h]) : 0.f;
                float e1 = ok1 ? __expf(acc[mi][ni][2*h+1] - mxr[mi][h]) : 0.f;
                acc[mi][ni][2*h] = e0; acc[mi][ni][2*h+1] = e1;
                sum_[mi][h] += e0 + e1;
            }
    }
    #pragma unroll
    for (int mi = 0; mi < 4; mi++)
        #pragma unroll
        for (int h = 0; h < 2; h++) {
            sum_[mi][h] += __shfl_xor_sync(0xffffffffu, sum_[mi][h], 1);
            sum_[mi][h] += __shfl_xor_sync(0xffffffffu, sum_[mi][h], 2);
        }
    if (c == 0) {
        #pragma unroll
        for (int mi = 0; mi < 4; mi++)
            #pragma unroll
            for (int h = 0; h < 2; h++)
                red[(w & 3) * 128 + wm0 + mi*16 + g + h*8] = sum_[mi][h];
    }
    __syncthreads();
    #pragma unroll
    for (int mi = 0; mi < 4; mi++) {
        #pragma unroll
        for (int h = 0; h < 2; h++) {
            int r = wm0 + mi*16 + g + h*8;
            float inv = 1.f / (red[r] + red[128 + r] + red[256 + r] + red[384 + r]);
            size_t t = m0 + r;
            #pragma unroll
            for (int ni = 0; ni < 4; ni++) {
                int cn = wn0 + ni*8 + c*2;
                if (cn < M_)   logits[t*LML_ + cn]   = acc[mi][ni][2*h]   * inv;
                if (cn+1 < M_) logits[t*LML_ + cn+1] = acc[mi][ni][2*h+1] * inv;
            }
        }
    }
}

// ==================== fused launches ====================
__global__ void __launch_bounds__(256, 2) k_fused1(
    const __half* A_lin, const __half* W1, const __half* W2,
    const float* b1, const float* b2,
    __half* TD, __half* X3,
    const int* q_data, const int* attempt_data,
    const int* hint_data, const int* hintTotal_data,
    const float* q_emb, const float* attempt_emb, const float* ht_emb,
    const __half* A_ea, const __half* Wea, const float* bea, __half* EA)
{
    extern __shared__ uint32_t sm[];
    int bx = blockIdx.x;
    if (bx < 2000) {
        dev_lin12(sm, bx * 128, A_lin, W1, W2, b1, b2, TD, X3,
                  q_data, attempt_data, hint_data, hintTotal_data,
                  q_emb, attempt_emb, ht_emb);
    } else {
        int idx = bx - 2000;
        dev_ea(sm, (idx % 1000) * 128, (idx / 1000) * 128, A_ea, Wea, bea, EA);
    }
}

__global__ void __launch_bounds__(256, 2) k_fused2(
    const __half* A_qp, const __half* W1, const __half* WM,
    const float* b1, const __half* TD,
    const int* time_data, const float* time_emb,
    __half* PredIn, float* logits,
    const __half* A_ea, const __half* Wea, const float* bea, __half* EA)
{
    extern __shared__ uint32_t sm[];
    int bx = blockIdx.x;
    if (bx < 1000) {
        dev_qplog(sm, bx * 128, A_qp, W1, WM, b1, TD, time_data, time_emb, PredIn, logits);
    } else {
        int idx = bx - 1000;
        dev_ea(sm, (idx % 1000) * 128, (2 + idx / 1000) * 128, A_ea, Wea, bea, EA);
    }
}

// ==================== readout GEMM (4-stage pipeline) ====================
__global__ void __launch_bounds__(256, 2) k_ro(
    const __half* __restrict__ A,
    const __half* __restrict__ W,
    const float* __restrict__ bias,
    const float* __restrict__ predW, float* __restrict__ predP)
{
    constexpr int NCH = 12, LDP = 192;
    extern __shared__ uint32_t sm[];
    uint32_t* As   = sm;                        // 4 * 2048
    uint32_t* Bs   = sm + 4 * 2048;             // 4 * 2048
    float*    sred = (float*)(sm + 8 * 2048);

    const int tid  = threadIdx.x;
    const int m0   = blockIdx.y * 128;
    const int n0   = blockIdx.x * 128;
    const int lane = tid & 31, w = tid >> 5;
    const int g    = lane >> 2, c = lane & 3;
    const int wm0  = (w >> 2) * 64;
    const int wn0  = (w & 3) * 32;
    const int srow = tid >> 2;
    const int grp  = tid & 3;

    const uint32_t* Ag = (const uint32_t*)A + (size_t)(m0 + srow) * LDP + grp * 4;
    const uint32_t* Wg = (const uint32_t*)W + (size_t)(n0 + srow) * LDP + grp * 4;
    const uint32_t asb = (uint32_t)__cvta_generic_to_shared(As) + (srow * 16 + grp * 4) * 4;
    const uint32_t bsb = (uint32_t)__cvta_generic_to_shared(Bs) + (srow * 16 + grp * 4) * 4;

    float acc[4][4][4];
    #pragma unroll
    for (int i = 0; i < 4; i++)
        #pragma unroll
        for (int j = 0; j < 4; j++)
            #pragma unroll
            for (int r = 0; r < 4; r++) acc[i][j][r] = 0.f;

    auto stage = [&](int ch, int s) {
        uint32_t ab = asb + s * 2048 * 4;
        cpa16(ab,               Ag + ch * 16);
        cpa16(ab + 64 * 16 * 4, Ag + (size_t)64 * LDP + ch * 16);
        uint32_t bb = bsb + s * 2048 * 4;
        cpa16(bb,               Wg + ch * 16);
        cpa16(bb + 64 * 16 * 4, Wg + (size_t)64 * LDP + ch * 16);
        asm volatile("cp.async.commit_group;");
    };

    stage(0, 0); stage(1, 1); stage(2, 2);
    #pragma unroll
    for (int ch = 0; ch < NCH; ch++) {
        asm volatile("cp.async.wait_group 2;");
        __syncthreads();
        if (ch + 3 < NCH) stage(ch + 3, (ch + 3) & 3);
        else asm volatile("cp.async.commit_group;");
        const uint32_t* as = As + (ch & 3) * 2048;
        const uint32_t* bs = Bs + (ch & 3) * 2048;
        uint4 alo[4], ahi[4];
        #pragma unroll
        for (int mi = 0; mi < 4; mi++) {
            alo[mi] = *(const uint4*)&as[(wm0 + mi*16 + g)     * 16 + c*4];
            ahi[mi] = *(const uint4*)&as[(wm0 + mi*16 + g + 8) * 16 + c*4];
        }
        #pragma unroll
        for (int ni = 0; ni < 4; ni++) {
            uint4 b = *(const uint4*)&bs[(wn0 + ni*8 + g) * 16 + c*4];
            #pragma unroll
            for (int mi = 0; mi < 4; mi++) {
                mma16(acc[mi][ni], alo[mi].x, ahi[mi].x, alo[mi].y, ahi[mi].y, b.x, b.y);
                mma16(acc[mi][ni], alo[mi].z, ahi[mi].z, alo[mi].w, ahi[mi].w, b.z, b.w);
            }
        }
    }

    float rsum[4][2];
    #pragma unroll
    for (int mi = 0; mi < 4; mi++) { rsum[mi][0] = 0.f; rsum[mi][1] = 0.f; }
    #pragma unroll
    for (int ni = 0; ni < 4; ni++) {
        int cn = n0 + wn0 + ni*8 + c*2;
        float b0 = __ldg(&bias[cn]),  b1v = __ldg(&bias[cn+1]);
        float p0 = __ldg(&predW[cn]), p1 = __ldg(&predW[cn+1]);
        #pragma unroll
        for (int mi = 0; mi < 4; mi++) {
            rsum[mi][0] += ftanh(acc[mi][ni][0] + b0) * p0 + ftanh(acc[mi][ni][1] + b1v) * p1;
            rsum[mi][1] += ftanh(acc[mi][ni][2] + b0) * p0 + ftanh(acc[mi][ni][3] + b1v) * p1;
        }
    }
    __syncthreads();
    if (tid < 128) sred[tid] = 0.f;
    __syncthreads();
    #pragma unroll
    for (int mi = 0; mi < 4; mi++)
        #pragma unroll
        for (int h = 0; h < 2; h++) {
            float v = rsum[mi][h];
            v += __shfl_xor_sync(0xffffffffu, v, 1);
            v += __shfl_xor_sync(0xffffffffu, v, 2);
            if (c == 0) atomicAdd(&sred[wm0 + mi*16 + h*8 + g], v);
        }
    __syncthreads();
    if (tid < 128) predP[(size_t)blockIdx.x * T_ + m0 + tid] = sred[tid];
}

// ==================== small kernels ====================
__global__ void k_prep(const float* __restrict__ eW, const float* __restrict__ eb,
                       const float* __restrict__ aW, const float* __restrict__ ab,
                       const float* __restrict__ d1W, const float* __restrict__ d2W,
                       const float* __restrict__ roW, const float* __restrict__ Mk)
{
    int i = blockIdx.x * blockDim.x + threadIdx.x;
    int stride = gridDim.x * blockDim.x;
    for (int j = i; j < NEA_*KEA_; j += stride) {
        int n = j / KEA_, k = j % KEA_;
        g_Wea[n*KEA_ + ph(k)] = __float2half((n < DV_) ? eW[n*KEA_ + k] : aW[(n - DV_)*KEA_ + k]);
    }
    for (int j = i; j < DQ_*DQ_; j += stride) {
        int n = j / DQ_, k = j % DQ_;
        g_Wd1[n*DQ_ + ph(k)] = __float2half(d1W[j]);
        g_Wd2[n*DQ_ + ph(k)] = __float2half(d2W[j]);
    }
    for (int j = i; j < F_*KRO_; j += stride) {
        int n = j / KRO_, k = j % KRO_;
        g_Wro[n*KRO_ + ph(k)] = __float2half(roW[j]);
    }
    for (int j = i; j < 128*DQ_; j += stride) {
        int n = j / DQ_, k = j % DQ_;
        g_Wmk[n*DQ_ + ph(k)] = __float2half(n < M_ ? Mk[n*DQ_ + k] : 0.f);
    }
    for (int j = i; j < NEA_; j += stride) g_bea[j] = (j < DV_) ? eb[j] : ab[j - DV_];
    if (i < 2) g_accum[i] = 0.f;
}

__global__ void k_gather1(const int* __restrict__ q_data, const int* __restrict__ qa_data,
                          const int* __restrict__ time_data, const int* __restrict__ attempt_data,
                          const int* __restrict__ hint_data, const int* __restrict__ hintTotal_data,
                          const float* __restrict__ q_emb, const float* __restrict__ qa_emb,
                          const float* __restrict__ time_emb, const float* __restrict__ attempt_emb,
                          const float* __restrict__ ht_emb)
{
    int t = blockIdx.x, d = threadIdx.x;
    int pd = ph(d);
    int qi = q_data[t], ti = time_data[t], ai = attempt_data[t];
    int hi = hint_data[t], hti = hintTotal_data[t];
    float qe  = q_emb[(size_t)qi*DQ_ + d];
    float te  = time_emb[(size_t)ti*DQ_ + d];
    float ae  = attempt_emb[(size_t)ai*DQ_ + d];
    float he  = ht_emb[(size_t)hi*DQ_ + d];
    float hte = ht_emb[(size_t)hti*DQ_ + d];
    g_bufX[(size_t)t*DQ_ + pd]      = __float2half(te + qe);
    g_bufX[(size_t)(T_+t)*DQ_ + pd] = __float2half(he + hte + ae + qe);
    int qai = qa_data[t];
    g_bufQA[(size_t)t*DV_ + pd]          = __float2half(qa_emb[(size_t)qai*DV_ + d]);
    g_bufQA[(size_t)t*DV_ + ph(d + DQ_)] = __float2half(qa_emb[(size_t)qai*DV_ + DQ_ + d]);
}

// DV split 2-way; per-warp ws; packed f32x2 FMA (R13 version — best known)
__global__ void __launch_bounds__(128) k_scan(const float* __restrict__ Mv0)
{
    int b = blockIdx.x;
    int tidw = threadIdx.x & 31;
    int wid  = threadIdx.x >> 5;
    int d = blockIdx.y * 128 + threadIdx.x;
    int pe = ph(d);
    int pa = ph(d + DV_);
    unsigned long long mv2[M_/2];
    #pragma unroll
    for (int j = 0; j < M_/2; j++)
        mv2[j] = pk2(Mv0[(2*j)*DV_ + d], Mv0[(2*j+1)*DV_ + d]);
    __shared__ float ws[4][2][64];
    size_t t0 = (size_t)b * S_;
    if (tidw < M_)      ws[wid][0][tidw]      = g_logits[t0*LML_ + tidw];
    if (tidw + 32 < M_) ws[wid][0][tidw + 32] = g_logits[t0*LML_ + tidw + 32];
    float e = __half2float(g_bufEA[t0*NEA_ + pe]);
    float a = __half2float(g_bufEA[t0*NEA_ + pa]);
    __syncwarp();
    for (int s = 0; s < S_; s++) {
        size_t t = t0 + s;
        float en = 0.f, an = 0.f;
        if (s + 1 < S_) {
            en = __half2float(g_bufEA[(t+1)*NEA_ + pe]);
            an = __half2float(g_bufEA[(t+1)*NEA_ + pa]);
            int nb = (s+1) & 1;
            if (tidw < M_)      ws[wid][nb][tidw]      = g_logits[(t+1)*LML_ + tidw];
            if (tidw + 32 < M_) ws[wid][nb][tidw + 32] = g_logits[(t+1)*LML_ + tidw + 32];
        }
        const float* wcur = ws[wid][s & 1];
        unsigned long long ne2 = pk2(-e, -e);
        unsigned long long a2  = pk2(a, a);
        unsigned long long rd2 = 0ull;
        #pragma unroll
        for (int j = 0; j < M_/2; j++) {
            float2 wp = *(const float2*)&wcur[2*j];
            unsigned long long w2 = pk2(wp.x, wp.y);
            rd2 = fma2(w2, mv2[j], rd2);
            mv2[j] = fma2(w2, fma2(ne2, mv2[j], a2), mv2[j]);
        }
        float2 rd = upk2(rd2);
        g_PredIn[t*KRO_ + pe] = __float2half(rd.x + rd.y);
        __syncwarp();
        e = en; a = an;
    }
}

__global__ void k_loss(const int* __restrict__ target, const float* __restrict__ pred_b,
                       float* __restrict__ out)
{
    int i = blockIdx.x * blockDim.x + threadIdx.x;
    float le = 0.f, cnt = 0.f;
    if (i < T_) {
        float p = g_predP[0][i] + g_predP[1][i] + g_predP[2][i] + g_predP[3][i] + pred_b[0];
        int tg = target[i];
        bool mask = tg >= 1;
        float y = mask ? (float)(tg - 1) : 0.f;
        float sig = 1.f / (1.f + expf(-p));
        out[1 + i]      = mask ? sig : 0.f;
        out[1 + T_ + i] = mask ? y   : 0.f;
        if (mask) {
            le = fmaxf(p, 0.f) + log1pf(expf(-fabsf(p))) - p * y;
            cnt = 1.f;
        }
    }
    __shared__ float sle[256], scn[256];
    sle[threadIdx.x] = le; scn[threadIdx.x] = cnt;
    __syncthreads();
    for (int o = 128; o; o >>= 1) {
        if (threadIdx.x < o) { sle[threadIdx.x] += sle[threadIdx.x + o]; scn[threadIdx.x] += scn[threadIdx.x + o]; }
        __syncthreads();
    }
    if (threadIdx.x == 0) { atomicAdd(&g_accum[0], sle[0]); atomicAdd(&g_accum[1], scn[0]); }
}

__global__ void k_final(float* __restrict__ out)
{
    out[0] = g_accum[0] / fmaxf(g_accum[1], 1.f);
}

// ==================== host ====================
extern "C" void kernel_launch(void* const* d_in, const int* in_sizes, int n_in,
                              void* d_out, int out_size)
{
    const int*   q_data      = (const int*)  d_in[0];
    const int*   qa_data     = (const int*)  d_in[1];
    const int*   target      = (const int*)  d_in[2];
    const int*   time_data   = (const int*)  d_in[3];
    const int*   attempt_data= (const int*)  d_in[4];
    const int*   hint_data   = (const int*)  d_in[5];
    const int*   hintTotal   = (const int*)  d_in[6];
    const float* q_emb       = (const float*)d_in[7];
    const float* qa_emb      = (const float*)d_in[8];
    const float* time_emb    = (const float*)d_in[9];
    const float* attempt_emb = (const float*)d_in[10];
    const float* ht_emb      = (const float*)d_in[11];
    const float* Mk          = (const float*)d_in[12];
    const float* Mv0         = (const float*)d_in[13];
    const float* diff_W      = (const float*)d_in[14];
    const float* diff_b      = (const float*)d_in[15];
    const float* diff2_W     = (const float*)d_in[16];
    const float* diff2_b     = (const float*)d_in[17];
    const float* erase_W     = (const float*)d_in[18];
    const float* erase_b     = (const float*)d_in[19];
    const float* add_W       = (const float*)d_in[20];
    const float* add_b       = (const float*)d_in[21];
    const float* read_W      = (const float*)d_in[22];
    const float* read_b      = (const float*)d_in[23];
    const float* pred_W      = (const float*)d_in[24];
    const float* pred_b      = (const float*)d_in[25];
    float* out = (float*)d_out;

    __half *bufX, *bufX3, *bufTD, *bufQA, *bufEA, *predin;
    __half *Wea, *Wd1, *Wd2, *Wro, *Wmk;
    float *logits, *predP, *bea;
    cudaGetSymbolAddress((void**)&bufX,   g_bufX);
    cudaGetSymbolAddress((void**)&bufX3,  g_bufX3);
    cudaGetSymbolAddress((void**)&bufTD,  g_bufTD);
    cudaGetSymbolAddress((void**)&bufQA,  g_bufQA);
    cudaGetSymbolAddress((void**)&bufEA,  g_bufEA);
    cudaGetSymbolAddress((void**)&predin, g_PredIn);
    cudaGetSymbolAddress((void**)&logits, g_logits);
    cudaGetSymbolAddress((void**)&predP,  g_predP);
    cudaGetSymbolAddress((void**)&Wea,    g_Wea);
    cudaGetSymbolAddress((void**)&Wd1,    g_Wd1);
    cudaGetSymbolAddress((void**)&Wd2,    g_Wd2);
    cudaGetSymbolAddress((void**)&Wro,    g_Wro);
    cudaGetSymbolAddress((void**)&Wmk,    g_Wmk);
    cudaGetSymbolAddress((void**)&bea,    g_bea);

    const int SML  = (6*2048 + 128*USTR) * 4;            // 90112
    const int SMQ  = (6*2048 + 128*USTR + 512) * 4;      // 92160
    const int SMR4 = (8*2048 + 128) * 4;                 // 66048 (4-stage ro)
    cudaFuncSetAttribute(k_fused1, cudaFuncAttributeMaxDynamicSharedMemorySize, SML);
    cudaFuncSetAttribute(k_fused2, cudaFuncAttributeMaxDynamicSharedMemorySize, SMQ);
    cudaFuncSetAttribute(k_ro,     cudaFuncAttributeMaxDynamicSharedMemorySize, SMR4);

    k_prep<<<1024, 256>>>(erase_W, erase_b, add_W, add_b, diff_W, diff2_W, read_W, Mk);
    k_gather1<<<T_, 128>>>(q_data, qa_data, time_data, attempt_data, hint_data, hintTotal,
                           q_emb, qa_emb, time_emb, attempt_emb, ht_emb);
    k_fused1<<<4000, 256, SML>>>(bufX, Wd1, Wd2, diff_b, diff2_b, bufTD, bufX3,
                                 q_data, attempt_data, hint_data, hintTotal,
                                 q_emb, attempt_emb, ht_emb,
                                 bufQA, Wea, bea, bufEA);
    k_fused2<<<3000, 256, SMQ>>>(bufX3, Wd1, Wmk, diff_b, bufTD,
                                 time_data, time_emb, predin, logits,
                                 bufQA, Wea, bea, bufEA);
    k_scan<<<dim3(B_, 2), 128>>>(Mv0);
    k_ro<<<dim3(4, 1000), 256, SMR4>>>(predin, Wro, read_b, pred_W, predP);
    k_loss<<<(T_ + 255)/256, 256>>>(target, pred_b, out);
    k_final<<<1, 1>>>(out);
}

// round 16
// speedup vs baseline: 1.1263x; 1.0026x over previous
#include <cuda_runtime.h>
#include <cuda_fp16.h>
#include <math.h>
#include <stdint.h>

#define B_   256
#define S_   500
#define T_   (B_*S_)        // 128000
#define DQ_  128
#define DV_  256
#define M_   50
#define F_   512
#define NEA_ 512
#define KEA_ 256
#define KRO_ 384
#define LML_ 64
#define USTR 80

// ---------------- scratch (device globals) ----------------
__device__ __half g_bufX [2*T_*DQ_];
__device__ __half g_bufX3[T_*DQ_];
__device__ __half g_bufTD[T_*DQ_];
__device__ __half g_bufQA[T_*DV_];
__device__ __half g_bufEA[T_*NEA_];
__device__ __half g_PredIn[T_*KRO_];
__device__ float  g_logits[T_*LML_];
__device__ float  g_predP[4][T_];
__device__ float  g_accum[2];
__device__ __half g_Wea[NEA_*KEA_];
__device__ __half g_Wd1[DQ_*DQ_];
__device__ __half g_Wd2[DQ_*DQ_];
__device__ __half g_Wro[F_*KRO_];
__device__ __half g_Wmk[128*DQ_];
__device__ float  g_bea[NEA_];

// ==================== helpers ====================
__device__ __forceinline__ int ph(int d) {
    int pair = d >> 1;
    int pi   = pair & 15;
    int pp   = (pair & ~15) | ((pi & 3) * 4 + (pi >> 2));
    return pp * 2 + (d & 1);
}
__device__ __forceinline__ int permc(int cn) {
    int pair = cn >> 1;
    int pi   = pair & 15;
    int pp   = (pair & ~15) | ((pi & 3) * 4 + (pi >> 2));
    return pp * 2;
}
__device__ __forceinline__ float fsig(float x) { return 1.f / (1.f + __expf(-x)); }
__device__ __forceinline__ float ftanh(float x) {
    float ax = fabsf(x);
    float t  = 1.f - 2.f / (1.f + __expf(2.f * ax));
    return copysignf(t, x);
}
__device__ __forceinline__ void mma16(float* d,
    uint32_t a0, uint32_t a1, uint32_t a2, uint32_t a3,
    uint32_t b0, uint32_t b1)
{
    asm volatile(
        "mma.sync.aligned.m16n8k16.row.col.f32.f16.f16.f32 "
        "{%0,%1,%2,%3},{%4,%5,%6,%7},{%8,%9},{%0,%1,%2,%3};"
        : "+f"(d[0]), "+f"(d[1]), "+f"(d[2]), "+f"(d[3])
        : "r"(a0), "r"(a1), "r"(a2), "r"(a3), "r"(b0), "r"(b1));
}
__device__ __forceinline__ void cpa16(uint32_t dst, const void* src) {
    asm volatile("cp.async.cg.shared.global [%0], [%1], 16;" :: "r"(dst), "l"(src));
}
// packed f32x2
__device__ __forceinline__ unsigned long long pk2(float lo, float hi) {
    unsigned long long r;
    asm("mov.b64 %0, {%1, %2};" : "=l"(r) : "f"(lo), "f"(hi));
    return r;
}
__device__ __forceinline__ float2 upk2(unsigned long long v) {
    float2 r;
    asm("mov.b64 {%0, %1}, %2;" : "=f"(r.x), "=f"(r.y) : "l"(v));
    return r;
}
__device__ __forceinline__ unsigned long long fma2(
    unsigned long long a, unsigned long long b, unsigned long long c)
{
    unsigned long long d;
    asm("fma.rn.f32x2 %0, %1, %2, %3;" : "=l"(d) : "l"(a), "l"(b), "l"(c));
    return d;
}

// ==================== device GEMM body: EA (K=256, perm store) ==============
__device__ __forceinline__ void dev_ea(uint32_t* sm, int m0, int n0,
    const __half* __restrict__ A, const __half* __restrict__ W,
    const float* __restrict__ bias, __half* __restrict__ C)
{
    constexpr int NCH = 8, LDP = 128;
    uint32_t* As = sm;
    uint32_t* Bs = sm + 3 * 2048;

    const int tid  = threadIdx.x;
    const int lane = tid & 31, w = tid >> 5;
    const int g    = lane >> 2, c = lane & 3;
    const int wm0  = (w >> 2) * 64;
    const int wn0  = (w & 3) * 32;
    const int srow = tid >> 2;
    const int grp  = tid & 3;

    const uint32_t* Ag = (const uint32_t*)A + (size_t)(m0 + srow) * LDP + grp * 4;
    const uint32_t* Wg = (const uint32_t*)W + (size_t)(n0 + srow) * LDP + grp * 4;
    const uint32_t asb = (uint32_t)__cvta_generic_to_shared(As) + (srow * 16 + grp * 4) * 4;
    const uint32_t bsb = (uint32_t)__cvta_generic_to_shared(Bs) + (srow * 16 + grp * 4) * 4;

    float acc[4][4][4];
    #pragma unroll
    for (int i = 0; i < 4; i++)
        #pragma unroll
        for (int j = 0; j < 4; j++)
            #pragma unroll
            for (int r = 0; r < 4; r++) acc[i][j][r] = 0.f;

    auto stage = [&](int ch, int s) {
        uint32_t ab = asb + s * 2048 * 4;
        cpa16(ab,               Ag + ch * 16);
        cpa16(ab + 64 * 16 * 4, Ag + (size_t)64 * LDP + ch * 16);
        uint32_t bb = bsb + s * 2048 * 4;
        cpa16(bb,               Wg + ch * 16);
        cpa16(bb + 64 * 16 * 4, Wg + (size_t)64 * LDP + ch * 16);
        asm volatile("cp.async.commit_group;");
    };

    stage(0, 0); stage(1, 1);
    #pragma unroll
    for (int ch = 0; ch < NCH; ch++) {
        asm volatile("cp.async.wait_group 1;");
        __syncthreads();
        if (ch + 2 < NCH) stage(ch + 2, (ch + 2) % 3);
        else asm volatile("cp.async.commit_group;");
        const uint32_t* as = As + (ch % 3) * 2048;
        const uint32_t* bs = Bs + (ch % 3) * 2048;
        uint4 alo[4], ahi[4];
        #pragma unroll
        for (int mi = 0; mi < 4; mi++) {
            alo[mi] = *(const uint4*)&as[(wm0 + mi*16 + g)     * 16 + c*4];
            ahi[mi] = *(const uint4*)&as[(wm0 + mi*16 + g + 8) * 16 + c*4];
        }
        #pragma unroll
        for (int ni = 0; ni < 4; ni++) {
            uint4 b = *(const uint4*)&bs[(wn0 + ni*8 + g) * 16 + c*4];
            #pragma unroll
            for (int mi = 0; mi < 4; mi++) {
                mma16(acc[mi][ni], alo[mi].x, ahi[mi].x, alo[mi].y, ahi[mi].y, b.x, b.y);
                mma16(acc[mi][ni], alo[mi].z, ahi[mi].z, alo[mi].w, ahi[mi].w, b.z, b.w);
            }
        }
    }

    #pragma unroll
    for (int ni = 0; ni < 4; ni++) {
        int cn  = n0 + wn0 + ni*8 + c*2;
        int cnp = permc(cn);
        float b0 = __ldg(&bias[cn]), b1 = __ldg(&bias[cn+1]);
        #pragma unroll
        for (int mi = 0; mi < 4; mi++) {
            int r0 = m0 + wm0 + mi*16 + g;
            float v0 = acc[mi][ni][0] + b0, v1 = acc[mi][ni][1] + b1;
            float v2 = acc[mi][ni][2] + b0, v3 = acc[mi][ni][3] + b1;
            if (cn < DV_) { v0 = fsig(v0); v1 = fsig(v1); v2 = fsig(v2); v3 = fsig(v3); }
            else          { v0 = ftanh(v0); v1 = ftanh(v1); v2 = ftanh(v2); v3 = ftanh(v3); }
            *(__half2*)&C[(size_t)r0    *NEA_ + cnp] = __floats2half2_rn(v0, v1);
            *(__half2*)&C[(size_t)(r0+8)*NEA_ + cnp] = __floats2half2_rn(v2, v3);
        }
    }
}

// ==================== device body: lin12 (GEMM2 weights prefetched) ========
__device__ __forceinline__ void dev_lin12(uint32_t* sm, int m0,
    const __half* __restrict__ A,
    const __half* __restrict__ W1, const __half* __restrict__ W2,
    const float* __restrict__ b1, const float* __restrict__ b2,
    __half* __restrict__ TD, __half* __restrict__ X3,
    const int* __restrict__ q_data, const int* __restrict__ attempt_data,
    const int* __restrict__ hint_data, const int* __restrict__ hintTotal_data,
    const float* __restrict__ q_emb, const float* __restrict__ attempt_emb,
    const float* __restrict__ ht_emb)
{
    uint32_t* Xs = sm;
    uint32_t* Bs = sm + 3*2048;
    uint32_t* Us = sm + 6*2048;

    const int tid  = threadIdx.x;
    const int lane = tid & 31, w = tid >> 5;
    const int g    = lane >> 2, c = lane & 3;
    const int wm0  = (w >> 2) * 64;
    const int wn0  = (w & 3) * 32;
    const int srow = tid >> 2;
    const int grp  = tid & 3;

    const uint32_t* Ag  = (const uint32_t*)A  + (size_t)(m0 + srow) * 64 + grp * 4;
    const uint32_t* W1g = (const uint32_t*)W1 + (size_t)srow * 64 + grp * 4;
    const uint32_t* W2g = (const uint32_t*)W2 + (size_t)srow * 64 + grp * 4;

    const uint32_t xsb = (uint32_t)__cvta_generic_to_shared(Xs) + (srow*16 + grp*4) * 4;
    const uint32_t bsb = (uint32_t)__cvta_generic_to_shared(Bs) + (srow*16 + grp*4) * 4;

    float acc[4][4][4];
    #pragma unroll
    for (int i = 0; i < 4; i++)
        #pragma unroll
        for (int j = 0; j < 4; j++)
            #pragma unroll
            for (int r = 0; r < 4; r++) acc[i][j][r] = 0.f;

    auto stage1 = [&](int ch, int s) {
        uint32_t xb = xsb + s * 2048 * 4;
        cpa16(xb,           Ag + ch * 16);
        cpa16(xb + 64*16*4, Ag + (size_t)64*64 + ch * 16);
        uint32_t bb = bsb + s * 2048 * 4;
        cpa16(bb,           W1g + ch * 16);
        cpa16(bb + 64*16*4, W1g + (size_t)64*64 + ch * 16);
        asm volatile("cp.async.commit_group;");
    };
    auto stage2 = [&](int ch, int s) {
        uint32_t bb = bsb + s * 2048 * 4;
        cpa16(bb,           W2g + ch * 16);
        cpa16(bb + 64*16*4, W2g + (size_t)64*64 + ch * 16);
        asm volatile("cp.async.commit_group;");
    };

    stage1(0, 0); stage1(1, 1);
    #pragma unroll
    for (int ch = 0; ch < 4; ch++) {
        asm volatile("cp.async.wait_group 1;");
        __syncthreads();
        if (ch + 2 < 4) stage1(ch + 2, (ch + 2) % 3);
        else asm volatile("cp.async.commit_group;");
        const uint32_t* xs = Xs + (ch % 3) * 2048;
        const uint32_t* bs = Bs + (ch % 3) * 2048;
        uint4 alo[4], ahi[4];
        #pragma unroll
        for (int mi = 0; mi < 4; mi++) {
            alo[mi] = *(const uint4*)&xs[(wm0 + mi*16 + g)     * 16 + c*4];
            ahi[mi] = *(const uint4*)&xs[(wm0 + mi*16 + g + 8) * 16 + c*4];
        }
        #pragma unroll
        for (int ni = 0; ni < 4; ni++) {
            uint4 b = *(const uint4*)&bs[(wn0 + ni*8 + g) * 16 + c*4];
            #pragma unroll
            for (int mi = 0; mi < 4; mi++) {
                mma16(acc[mi][ni], alo[mi].x, ahi[mi].x, alo[mi].y, ahi[mi].y, b.x, b.y);
                mma16(acc[mi][ni], alo[mi].z, ahi[mi].z, alo[mi].w, ahi[mi].w, b.z, b.w);
            }
        }
    }
    asm volatile("cp.async.wait_group 0;");
    __syncthreads();                 // all warps done reading Bs before refill
    stage2(0, 0); stage2(1, 1);      // prefetch W2 BEHIND the epilogue below

    #pragma unroll
    for (int ni = 0; ni < 4; ni++) {
        int cn = wn0 + ni*8 + c*2;
        float bb0 = __ldg(&b1[cn]), bb1 = __ldg(&b1[cn+1]);
        int pw = permc(cn) >> 1;
        #pragma unroll
        for (int mi = 0; mi < 4; mi++) {
            int r0 = wm0 + mi*16 + g;
            __half2 h0 = __floats2half2_rn(ftanh(acc[mi][ni][0] + bb0), ftanh(acc[mi][ni][1] + bb1));
            __half2 h1 = __floats2half2_rn(ftanh(acc[mi][ni][2] + bb0), ftanh(acc[mi][ni][3] + bb1));
            Us[r0*USTR + pw]     = *(uint32_t*)&h0;
            Us[(r0+8)*USTR + pw] = *(uint32_t*)&h1;
            acc[mi][ni][0] = acc[mi][ni][1] = acc[mi][ni][2] = acc[mi][ni][3] = 0.f;
        }
    }
    __syncthreads();

    #pragma unroll
    for (int ch = 0; ch < 4; ch++) {
        asm volatile("cp.async.wait_group 1;");
        __syncthreads();
        if (ch + 2 < 4) stage2(ch + 2, (ch + 2) % 3);
        else asm volatile("cp.async.commit_group;");
        const uint32_t* bs = Bs + (ch % 3) * 2048;
        uint4 alo[4], ahi[4];
        #pragma unroll
        for (int mi = 0; mi < 4; mi++) {
            alo[mi] = *(const uint4*)&Us[(wm0 + mi*16 + g)     * USTR + ch*16 + c*4];
            ahi[mi] = *(const uint4*)&Us[(wm0 + mi*16 + g + 8) * USTR + ch*16 + c*4];
        }
        #pragma unroll
        for (int ni = 0; ni < 4; ni++) {
            uint4 b = *(const uint4*)&bs[(wn0 + ni*8 + g) * 16 + c*4];
            #pragma unroll
            for (int mi = 0; mi < 4; mi++) {
                mma16(acc[mi][ni], alo[mi].x, ahi[mi].x, alo[mi].y, ahi[mi].y, b.x, b.y);
                mma16(acc[mi][ni], alo[mi].z, ahi[mi].z, alo[mi].w, ahi[mi].w, b.z, b.w);
            }
        }
    }

    const bool isdiff = (m0 >= T_);
    #pragma unroll
    for (int mi = 0; mi < 4; mi++) {
        #pragma unroll
        for (int h = 0; h < 2; h++) {
            int r = wm0 + mi*16 + g + h*8;
            int t = m0 + r;
            if (!isdiff) {
                #pragma unroll
                for (int ni = 0; ni < 4; ni++) {
                    int cn = wn0 + ni*8 + c*2;
                    float v0 = fsig(acc[mi][ni][2*h]   + __ldg(&b2[cn]));
                    float v1 = fsig(acc[mi][ni][2*h+1] + __ldg(&b2[cn+1]));
                    *(__half2*)&TD[(size_t)t*DQ_ + cn] = __floats2half2_rn(v0, v1);
                }
            } else {
                int tt = t - T_;
                int qi = q_data[tt], ai = attempt_data[tt];
                int hi = hint_data[tt], hti = hintTotal_data[tt];
                #pragma unroll
                for (int ni = 0; ni < 4; ni++) {
                    int cn = wn0 + ni*8 + c*2;
                    float v0 = fsig(acc[mi][ni][2*h]   + __ldg(&b2[cn]));
                    float v1 = fsig(acc[mi][ni][2*h+1] + __ldg(&b2[cn+1]));
                    float qe0 = q_emb[(size_t)qi*DQ_ + cn],   qe1 = q_emb[(size_t)qi*DQ_ + cn+1];
                    float g0  = attempt_emb[(size_t)ai*DQ_ + cn]
                              + ht_emb[(size_t)hi*DQ_ + cn] + ht_emb[(size_t)hti*DQ_ + cn];
                    float g1  = attempt_emb[(size_t)ai*DQ_ + cn+1]
                              + ht_emb[(size_t)hi*DQ_ + cn+1] + ht_emb[(size_t)hti*DQ_ + cn+1];
                    *(__half2*)&X3[(size_t)tt*DQ_ + permc(cn)] =
                        __floats2half2_rn(fmaf(v0, g0, qe0), fmaf(v1, g1, qe1));
                }
            }
        }
    }
}

// ==================== device body: qplog (WM prefetched) ====================
__device__ __forceinline__ void dev_qplog(uint32_t* sm, int m0,
    const __half* __restrict__ A,
    const __half* __restrict__ W1, const __half* __restrict__ WM,
    const float* __restrict__ b1, const __half* __restrict__ TD,
    const int* __restrict__ time_data, const float* __restrict__ time_emb,
    __half* __restrict__ PredIn, float* __restrict__ logits)
{
    uint32_t* Xs  = sm;
    uint32_t* Bs  = sm + 3*2048;
    uint32_t* Us  = sm + 6*2048;
    float*    red = (float*)(sm + 6*2048 + 128*USTR);

    const int tid  = threadIdx.x;
    const int lane = tid & 31, w = tid >> 5;
    const int g    = lane >> 2, c = lane & 3;
    const int wm0  = (w >> 2) * 64;
    const int wn0  = (w & 3) * 32;
    const int srow = tid >> 2;
    const int grp  = tid & 3;

    const uint32_t* Ag  = (const uint32_t*)A  + (size_t)(m0 + srow) * 64 + grp * 4;
    const uint32_t* W1g = (const uint32_t*)W1 + (size_t)srow * 64 + grp * 4;
    const uint32_t* WMg = (const uint32_t*)WM + (size_t)srow * 64 + grp * 4;

    const uint32_t xsb = (uint32_t)__cvta_generic_to_shared(Xs) + (srow*16 + grp*4) * 4;
    const uint32_t bsb = (uint32_t)__cvta_generic_to_shared(Bs) + (srow*16 + grp*4) * 4;

    float acc[4][4][4];
    #pragma unroll
    for (int i = 0; i < 4; i++)
        #pragma unroll
        for (int j = 0; j < 4; j++)
            #pragma unroll
            for (int r = 0; r < 4; r++) acc[i][j][r] = 0.f;

    auto stage1 = [&](int ch, int s) {
        uint32_t xb = xsb + s * 2048 * 4;
        cpa16(xb,           Ag + ch * 16);
        cpa16(xb + 64*16*4, Ag + (size_t)64*64 + ch * 16);
        uint32_t bb = bsb + s * 2048 * 4;
        cpa16(bb,           W1g + ch * 16);
        cpa16(bb + 64*16*4, W1g + (size_t)64*64 + ch * 16);
        asm volatile("cp.async.commit_group;");
    };
    auto stage2 = [&](int ch, int s) {
        uint32_t bb = bsb + s * 2048 * 4;
        cpa16(bb,           WMg + ch * 16);
        cpa16(bb + 64*16*4, WMg + (size_t)64*64 + ch * 16);
        asm volatile("cp.async.commit_group;");
    };

    stage1(0, 0); stage1(1, 1);
    #pragma unroll
    for (int ch = 0; ch < 4; ch++) {
        asm volatile("cp.async.wait_group 1;");
        __syncthreads();
        if (ch + 2 < 4) stage1(ch + 2, (ch + 2) % 3);
        else asm volatile("cp.async.commit_group;");
        const uint32_t* xs = Xs + (ch % 3) * 2048;
        const uint32_t* bs = Bs + (ch % 3) * 2048;
        uint4 alo[4], ahi[4];
        #pragma unroll
        for (int mi = 0; mi < 4; mi++) {
            alo[mi] = *(const uint4*)&xs[(wm0 + mi*16 + g)     * 16 + c*4];
            ahi[mi] = *(const uint4*)&xs[(wm0 + mi*16 + g + 8) * 16 + c*4];
        }
        #pragma unroll
        for (int ni = 0; ni < 4; ni++) {
            uint4 b = *(const uint4*)&bs[(wn0 + ni*8 + g) * 16 + c*4];
            #pragma unroll
            for (int mi = 0; mi < 4; mi++) {
                mma16(acc[mi][ni], alo[mi].x, ahi[mi].x, alo[mi].y, ahi[mi].y, b.x, b.y);
                mma16(acc[mi][ni], alo[mi].z, ahi[mi].z, alo[mi].w, ahi[mi].w, b.z, b.w);
            }
        }
    }
    asm volatile("cp.async.wait_group 0;");
    __syncthreads();
    stage2(0, 0); stage2(1, 1);      // prefetch WM behind the epilogue

    #pragma unroll
    for (int mi = 0; mi < 4; mi++) {
        #pragma unroll
        for (int h = 0; h < 2; h++) {
            int r = wm0 + mi*16 + g + h*8;
            int t = m0 + r;
            int ti = time_data[t];
            #pragma unroll
            for (int ni = 0; ni < 4; ni++) {
                int cn = wn0 + ni*8 + c*2;
                float q0 = acc[mi][ni][2*h]   + __ldg(&b1[cn]);
                float q1 = acc[mi][ni][2*h+1] + __ldg(&b1[cn+1]);
                __half2 hq = __floats2half2_rn(q0, q1);
                Us[r*USTR + (permc(cn) >> 1)] = *(uint32_t*)&hq;
                float2 qp2 = __half22float2(hq);
                __half2 tfh = *(const __half2*)&TD[(size_t)t*DQ_ + cn];
                float2 tf2 = __half22float2(tfh);
                float te0 = time_emb[(size_t)ti*DQ_ + cn], te1 = time_emb[(size_t)ti*DQ_ + cn+1];
                *(__half2*)&PredIn[(size_t)t*KRO_ + DV_ + permc(cn)] =
                    __floats2half2_rn(fmaf(tf2.x, te0, qp2.x), fmaf(tf2.y, te1, qp2.y));
                acc[mi][ni][2*h] = 0.f; acc[mi][ni][2*h+1] = 0.f;
            }
        }
    }
    __syncthreads();

    #pragma unroll
    for (int ch = 0; ch < 4; ch++) {
        asm volatile("cp.async.wait_group 1;");
        __syncthreads();
        if (ch + 2 < 4) stage2(ch + 2, (ch + 2) % 3);
        else asm volatile("cp.async.commit_group;");
        const uint32_t* bs = Bs + (ch % 3) * 2048;
        uint4 alo[4], ahi[4];
        #pragma unroll
        for (int mi = 0; mi < 4; mi++) {
            alo[mi] = *(const uint4*)&Us[(wm0 + mi*16 + g)     * USTR + ch*16 + c*4];
            ahi[mi] = *(const uint4*)&Us[(wm0 + mi*16 + g + 8) * USTR + ch*16 + c*4];
        }
        #pragma unroll
        for (int ni = 0; ni < 4; ni++) {
            uint4 b = *(const uint4*)&bs[(wn0 + ni*8 + g) * 16 + c*4];
            #pragma unroll
            for (int mi = 0; mi < 4; mi++) {
                mma16(acc[mi][ni], alo[mi].x, ahi[mi].x, alo[mi].y, ahi[mi].y, b.x, b.y);
                mma16(acc[mi][ni], alo[mi].z, ahi[mi].z, alo[mi].w, ahi[mi].w, b.z, b.w);
            }
        }
    }

    float mx[4][2];
    #pragma unroll
    for (int mi = 0; mi < 4; mi++) { mx[mi][0] = -1e30f; mx[mi][1] = -1e30f; }
    #pragma unroll
    for (int ni = 0; ni < 4; ni++) {
        int cn = wn0 + ni*8 + c*2;
        bool ok0 = cn < M_, ok1 = (cn+1) < M_;
        #pragma unroll
        for (int mi = 0; mi < 4; mi++)
            #pragma unroll
            for (int h = 0; h < 2; h++) {
                if (ok0) mx[mi][h] = fmaxf(mx[mi][h], acc[mi][ni][2*h]);
                if (ok1) mx[mi][h] = fmaxf(mx[mi][h], acc[mi][ni][2*h+1]);
            }
    }
    #pragma unroll
    for (int mi = 0; mi < 4; mi++)
        #pragma unroll
        for (int h = 0; h < 2; h++) {
            mx[mi][h] = fmaxf(mx[mi][h], __shfl_xor_sync(0xffffffffu, mx[mi][h], 1));
            mx[mi][h] = fmaxf(mx[mi][h], __shfl_xor_sync(0xffffffffu, mx[mi][h], 2));
        }
    __syncthreads();
    if (c == 0) {
        #pragma unroll
        for (int mi = 0; mi < 4; mi++)
            #pragma unroll
            for (int h = 0; h < 2; h++)
                red[(w & 3) * 128 + wm0 + mi*16 + g + h*8] = mx[mi][h];
    }
    __syncthreads();
    float mxr[4][2];
    #pragma unroll
    for (int mi = 0; mi < 4; mi++)
        #pragma unroll
        for (int h = 0; h < 2; h++) {
            int r = wm0 + mi*16 + g + h*8;
            mxr[mi][h] = fmaxf(fmaxf(red[r], red[128 + r]), fmaxf(red[256 + r], red[384 + r]));
        }
    __syncthreads();
    float sum_[4][2];
    #pragma unroll
    for (int mi = 0; mi < 4; mi++) { sum_[mi][0] = 0.f; sum_[mi][1] = 0.f; }
    #pragma unroll
    for (int ni = 0; ni < 4; ni++) {
        int cn = wn0 + ni*8 + c*2;
        bool ok0 = cn < M_, ok1 = (cn+1) < M_;
        #pragma unroll
        for (int mi = 0; mi < 4; mi++)
            #pragma unroll
            for (int h = 0; h < 2; h++) {
                float e0 = ok0 ? __expf(acc[mi][ni][2*h]   - mxr[mi][h]) : 0.f;
                float e1 = ok1 ? __expf(acc[mi][ni][2*h+1] - mxr[mi][h]) : 0.f;
                acc[mi][ni][2*h] = e0; acc[mi][ni][2*h+1] = e1;
                sum_[mi][h] += e0 + e1;
            }
    }
    #pragma unroll
    for (int mi = 0; mi < 4; mi++)
        #pragma unroll
        for (int h = 0; h < 2; h++) {
            sum_[mi][h] += __shfl_xor_sync(0xffffffffu, sum_[mi][h], 1);
            sum_[mi][h] += __shfl_xor_sync(0xffffffffu, sum_[mi][h], 2);
        }
    if (c == 0) {
        #pragma unroll
        for (int mi = 0; mi < 4; mi++)
            #pragma unroll
            for (int h = 0; h < 2; h++)
                red[(w & 3) * 128 + wm0 + mi*16 + g + h*8] = sum_[mi][h];
    }
    __syncthreads();
    #pragma unroll
    for (int mi = 0; mi < 4; mi++) {
        #pragma unroll
        for (int h = 0; h < 2; h++) {
            int r = wm0 + mi*16 + g + h*8;
            float inv = 1.f / (red[r] + red[128 + r] + red[256 + r] + red[384 + r]);
            size_t t = m0 + r;
            #pragma unroll
            for (int ni = 0; ni < 4; ni++) {
                int cn = wn0 + ni*8 + c*2;
                if (cn < M_)   logits[t*LML_ + cn]   = acc[mi][ni][2*h]   * inv;
                if (cn+1 < M_) logits[t*LML_ + cn+1] = acc[mi][ni][2*h+1] * inv;
            }
        }
    }
}

// ==================== fused launches ====================
__global__ void __launch_bounds__(256, 2) k_fused1(
    const __half* A_lin, const __half* W1, const __half* W2,
    const float* b1, const float* b2,
    __half* TD, __half* X3,
    const int* q_data, const int* attempt_data,
    const int* hint_data, const int* hintTotal_data,
    const float* q_emb, const float* attempt_emb, const float* ht_emb,
    const __half* A_ea, const __half* Wea, const float* bea, __half* EA)
{
    extern __shared__ uint32_t sm[];
    int bx = blockIdx.x;
    if (bx < 2000) {
        dev_lin12(sm, bx * 128, A_lin, W1, W2, b1, b2, TD, X3,
                  q_data, attempt_data, hint_data, hintTotal_data,
                  q_emb, attempt_emb, ht_emb);
    } else {
        int idx = bx - 2000;
        dev_ea(sm, (idx % 1000) * 128, (idx / 1000) * 128, A_ea, Wea, bea, EA);
    }
}

__global__ void __launch_bounds__(256, 2) k_fused2(
    const __half* A_qp, const __half* W1, const __half* WM,
    const float* b1, const __half* TD,
    const int* time_data, const float* time_emb,
    __half* PredIn, float* logits,
    const __half* A_ea, const __half* Wea, const float* bea, __half* EA)
{
    extern __shared__ uint32_t sm[];
    int bx = blockIdx.x;
    if (bx < 1000) {
        dev_qplog(sm, bx * 128, A_qp, W1, WM, b1, TD, time_data, time_emb, PredIn, logits);
    } else {
        int idx = bx - 1000;
        dev_ea(sm, (idx % 1000) * 128, (2 + idx / 1000) * 128, A_ea, Wea, bea, EA);
    }
}

// ==================== readout GEMM (3-stage, R13-proven) ====================
__global__ void __launch_bounds__(256, 2) k_ro(
    const __half* __restrict__ A,
    const __half* __restrict__ W,
    const float* __restrict__ bias,
    const float* __restrict__ predW, float* __restrict__ predP)
{
    constexpr int NCH = 12, LDP = 192;
    extern __shared__ uint32_t sm[];
    uint32_t* As   = sm;
    uint32_t* Bs   = sm + 3 * 2048;
    float*    sred = (float*)(sm + 6 * 2048);

    const int tid  = threadIdx.x;
    const int m0   = blockIdx.y * 128;
    const int n0   = blockIdx.x * 128;
    const int lane = tid & 31, w = tid >> 5;
    const int g    = lane >> 2, c = lane & 3;
    const int wm0  = (w >> 2) * 64;
    const int wn0  = (w & 3) * 32;
    const int srow = tid >> 2;
    const int grp  = tid & 3;

    const uint32_t* Ag = (const uint32_t*)A + (size_t)(m0 + srow) * LDP + grp * 4;
    const uint32_t* Wg = (const uint32_t*)W + (size_t)(n0 + srow) * LDP + grp * 4;
    const uint32_t asb = (uint32_t)__cvta_generic_to_shared(As) + (srow * 16 + grp * 4) * 4;
    const uint32_t bsb = (uint32_t)__cvta_generic_to_shared(Bs) + (srow * 16 + grp * 4) * 4;

    float acc[4][4][4];
    #pragma unroll
    for (int i = 0; i < 4; i++)
        #pragma unroll
        for (int j = 0; j < 4; j++)
            #pragma unroll
            for (int r = 0; r < 4; r++) acc[i][j][r] = 0.f;

    auto stage = [&](int ch, int s) {
        uint32_t ab = asb + s * 2048 * 4;
        cpa16(ab,               Ag + ch * 16);
        cpa16(ab + 64 * 16 * 4, Ag + (size_t)64 * LDP + ch * 16);
        uint32_t bb = bsb + s * 2048 * 4;
        cpa16(bb,               Wg + ch * 16);
        cpa16(bb + 64 * 16 * 4, Wg + (size_t)64 * LDP + ch * 16);
        asm volatile("cp.async.commit_group;");
    };

    stage(0, 0); stage(1, 1);
    #pragma unroll
    for (int ch = 0; ch < NCH; ch++) {
        asm volatile("cp.async.wait_group 1;");
        __syncthreads();
        if (ch + 2 < NCH) stage(ch + 2, (ch + 2) % 3);
        else asm volatile("cp.async.commit_group;");
        const uint32_t* as = As + (ch % 3) * 2048;
        const uint32_t* bs = Bs + (ch % 3) * 2048;
        uint4 alo[4], ahi[4];
        #pragma unroll
        for (int mi = 0; mi < 4; mi++) {
            alo[mi] = *(const uint4*)&as[(wm0 + mi*16 + g)     * 16 + c*4];
            ahi[mi] = *(const uint4*)&as[(wm0 + mi*16 + g + 8) * 16 + c*4];
        }
        #pragma unroll
        for (int ni = 0; ni < 4; ni++) {
            uint4 b = *(const uint4*)&bs[(wn0 + ni*8 + g) * 16 + c*4];
            #pragma unroll
            for (int mi = 0; mi < 4; mi++) {
                mma16(acc[mi][ni], alo[mi].x, ahi[mi].x, alo[mi].y, ahi[mi].y, b.x, b.y);
                mma16(acc[mi][ni], alo[mi].z, ahi[mi].z, alo[mi].w, ahi[mi].w, b.z, b.w);
            }
        }
    }

    float rsum[4][2];
    #pragma unroll
    for (int mi = 0; mi < 4; mi++) { rsum[mi][0] = 0.f; rsum[mi][1] = 0.f; }
    #pragma unroll
    for (int ni = 0; ni < 4; ni++) {
        int cn = n0 + wn0 + ni*8 + c*2;
        float b0 = __ldg(&bias[cn]),  b1v = __ldg(&bias[cn+1]);
        float p0 = __ldg(&predW[cn]), p1 = __ldg(&predW[cn+1]);
        #pragma unroll
        for (int mi = 0; mi < 4; mi++) {
            rsum[mi][0] += ftanh(acc[mi][ni][0] + b0) * p0 + ftanh(acc[mi][ni][1] + b1v) * p1;
            rsum[mi][1] += ftanh(acc[mi][ni][2] + b0) * p0 + ftanh(acc[mi][ni][3] + b1v) * p1;
        }
    }
    __syncthreads();
    if (tid < 128) sred[tid] = 0.f;
    __syncthreads();
    #pragma unroll
    for (int mi = 0; mi < 4; mi++)
        #pragma unroll
        for (int h = 0; h < 2; h++) {
            float v = rsum[mi][h];
            v += __shfl_xor_sync(0xffffffffu, v, 1);
            v += __shfl_xor_sync(0xffffffffu, v, 2);
            if (c == 0) atomicAdd(&sred[wm0 + mi*16 + h*8 + g], v);
        }
    __syncthreads();
    if (tid < 128) predP[(size_t)blockIdx.x * T_ + m0 + tid] = sred[tid];
}

// ==================== merged gather + prep (one launch) ====================
__global__ void k_gp(const int* __restrict__ q_data, const int* __restrict__ qa_data,
                     const int* __restrict__ time_data, const int* __restrict__ attempt_data,
                     const int* __restrict__ hint_data, const int* __restrict__ hintTotal_data,
                     const float* __restrict__ q_emb, const float* __restrict__ qa_emb,
                     const float* __restrict__ time_emb, const float* __restrict__ attempt_emb,
                     const float* __restrict__ ht_emb,
                     const float* __restrict__ eW, const float* __restrict__ eb,
                     const float* __restrict__ aW, const float* __restrict__ ab,
                     const float* __restrict__ d1W, const float* __restrict__ d2W,
                     const float* __restrict__ roW, const float* __restrict__ Mk)
{
    int bx = blockIdx.x;
    if (bx < T_) {
        int t = bx, d = threadIdx.x;
        int pd = ph(d);
        int qi = q_data[t], ti = time_data[t], ai = attempt_data[t];
        int hi = hint_data[t], hti = hintTotal_data[t];
        float qe  = q_emb[(size_t)qi*DQ_ + d];
        float te  = time_emb[(size_t)ti*DQ_ + d];
        float ae  = attempt_emb[(size_t)ai*DQ_ + d];
        float he  = ht_emb[(size_t)hi*DQ_ + d];
        float hte = ht_emb[(size_t)hti*DQ_ + d];
        g_bufX[(size_t)t*DQ_ + pd]      = __float2half(te + qe);
        g_bufX[(size_t)(T_+t)*DQ_ + pd] = __float2half(he + hte + ae + qe);
        int qai = qa_data[t];
        g_bufQA[(size_t)t*DV_ + pd]          = __float2half(qa_emb[(size_t)qai*DV_ + d]);
        g_bufQA[(size_t)t*DV_ + ph(d + DQ_)] = __float2half(qa_emb[(size_t)qai*DV_ + DQ_ + d]);
    } else {
        int i = (bx - T_) * 128 + threadIdx.x;
        int stride = 2048 * 128;
        for (int j = i; j < NEA_*KEA_; j += stride) {
            int n = j / KEA_, k = j % KEA_;
            g_Wea[n*KEA_ + ph(k)] = __float2half((n < DV_) ? eW[n*KEA_ + k] : aW[(n - DV_)*KEA_ + k]);
        }
        for (int j = i; j < DQ_*DQ_; j += stride) {
            int n = j / DQ_, k = j % DQ_;
            g_Wd1[n*DQ_ + ph(k)] = __float2half(d1W[j]);
            g_Wd2[n*DQ_ + ph(k)] = __float2half(d2W[j]);
        }
        for (int j = i; j < F_*KRO_; j += stride) {
            int n = j / KRO_, k = j % KRO_;
            g_Wro[n*KRO_ + ph(k)] = __float2half(roW[j]);
        }
        for (int j = i; j < 128*DQ_; j += stride) {
            int n = j / DQ_, k = j % DQ_;
            g_Wmk[n*DQ_ + ph(k)] = __float2half(n < M_ ? Mk[n*DQ_ + k] : 0.f);
        }
        for (int j = i; j < NEA_; j += stride) g_bea[j] = (j < DV_) ? eb[j] : ab[j - DV_];
        if (i < 2) g_accum[i] = 0.f;
    }
}

// DV split 2-way; per-warp ws; packed f32x2 FMA (R13 version — best known)
__global__ void __launch_bounds__(128) k_scan(const float* __restrict__ Mv0)
{
    int b = blockIdx.x;
    int tidw = threadIdx.x & 31;
    int wid  = threadIdx.x >> 5;
    int d = blockIdx.y * 128 + threadIdx.x;
    int pe = ph(d);
    int pa = ph(d + DV_);
    unsigned long long mv2[M_/2];
    #pragma unroll
    for (int j = 0; j < M_/2; j++)
        mv2[j] = pk2(Mv0[(2*j)*DV_ + d], Mv0[(2*j+1)*DV_ + d]);
    __shared__ float ws[4][2][64];
    size_t t0 = (size_t)b * S_;
    if (tidw < M_)      ws[wid][0][tidw]      = g_logits[t0*LML_ + tidw];
    if (tidw + 32 < M_) ws[wid][0][tidw + 32] = g_logits[t0*LML_ + tidw + 32];
    float e = __half2float(g_bufEA[t0*NEA_ + pe]);
    float a = __half2float(g_bufEA[t0*NEA_ + pa]);
    __syncwarp();
    for (int s = 0; s < S_; s++) {
        size_t t = t0 + s;
        float en = 0.f, an = 0.f;
        if (s + 1 < S_) {
            en = __half2float(g_bufEA[(t+1)*NEA_ + pe]);
            an = __half2float(g_bufEA[(t+1)*NEA_ + pa]);
            int nb = (s+1) & 1;
            if (tidw < M_)      ws[wid][nb][tidw]      = g_logits[(t+1)*LML_ + tidw];
            if (tidw + 32 < M_) ws[wid][nb][tidw + 32] = g_logits[(t+1)*LML_ + tidw + 32];
        }
        const float* wcur = ws[wid][s & 1];
        unsigned long long ne2 = pk2(-e, -e);
        unsigned long long a2  = pk2(a, a);
        unsigned long long rd2 = 0ull;
        #pragma unroll
        for (int j = 0; j < M_/2; j++) {
            float2 wp = *(const float2*)&wcur[2*j];
            unsigned long long w2 = pk2(wp.x, wp.y);
            rd2 = fma2(w2, mv2[j], rd2);
            mv2[j] = fma2(w2, fma2(ne2, mv2[j], a2), mv2[j]);
        }
        float2 rd = upk2(rd2);
        g_PredIn[t*KRO_ + pe] = __float2half(rd.x + rd.y);
        __syncwarp();
        e = en; a = an;
    }
}

__global__ void k_loss(const int* __restrict__ target, const float* __restrict__ pred_b,
                       float* __restrict__ out)
{
    int i = blockIdx.x * blockDim.x + threadIdx.x;
    float le = 0.f, cnt = 0.f;
    if (i < T_) {
        float p = g_predP[0][i] + g_predP[1][i] + g_predP[2][i] + g_predP[3][i] + pred_b[0];
        int tg = target[i];
        bool mask = tg >= 1;
        float y = mask ? (float)(tg - 1) : 0.f;
        float sig = 1.f / (1.f + expf(-p));
        out[1 + i]      = mask ? sig : 0.f;
        out[1 + T_ + i] = mask ? y   : 0.f;
        if (mask) {
            le = fmaxf(p, 0.f) + log1pf(expf(-fabsf(p))) - p * y;
            cnt = 1.f;
        }
    }
    __shared__ float sle[256], scn[256];
    sle[threadIdx.x] = le; scn[threadIdx.x] = cnt;
    __syncthreads();
    for (int o = 128; o; o >>= 1) {
        if (threadIdx.x < o) { sle[threadIdx.x] += sle[threadIdx.x + o]; scn[threadIdx.x] += scn[threadIdx.x + o]; }
        __syncthreads();
    }
    if (threadIdx.x == 0) { atomicAdd(&g_accum[0], sle[0]); atomicAdd(&g_accum[1], scn[0]); }
}

__global__ void k_final(float* __restrict__ out)
{
    out[0] = g_accum[0] / fmaxf(g_accum[1], 1.f);
}

// ==================== host ====================
extern "C" void kernel_launch(void* const* d_in, const int* in_sizes, int n_in,
                              void* d_out, int out_size)
{
    const int*   q_data      = (const int*)  d_in[0];
    const int*   qa_data     = (const int*)  d_in[1];
    const int*   target      = (const int*)  d_in[2];
    const int*   time_data   = (const int*)  d_in[3];
    const int*   attempt_data= (const int*)  d_in[4];
    const int*   hint_data   = (const int*)  d_in[5];
    const int*   hintTotal   = (const int*)  d_in[6];
    const float* q_emb       = (const float*)d_in[7];
    const float* qa_emb      = (const float*)d_in[8];
    const float* time_emb    = (const float*)d_in[9];
    const float* attempt_emb = (const float*)d_in[10];
    const float* ht_emb      = (const float*)d_in[11];
    const float* Mk          = (const float*)d_in[12];
    const float* Mv0         = (const float*)d_in[13];
    const float* diff_W      = (const float*)d_in[14];
    const float* diff_b      = (const float*)d_in[15];
    const float* diff2_W     = (const float*)d_in[16];
    const float* diff2_b     = (const float*)d_in[17];
    const float* erase_W     = (const float*)d_in[18];
    const float* erase_b     = (const float*)d_in[19];
    const float* add_W       = (const float*)d_in[20];
    const float* add_b       = (const float*)d_in[21];
    const float* read_W      = (const float*)d_in[22];
    const float* read_b      = (const float*)d_in[23];
    const float* pred_W      = (const float*)d_in[24];
    const float* pred_b      = (const float*)d_in[25];
    float* out = (float*)d_out;

    __half *bufX, *bufX3, *bufTD, *bufQA, *bufEA, *predin;
    __half *Wea, *Wd1, *Wd2, *Wro, *Wmk;
    float *logits, *predP, *bea;
    cudaGetSymbolAddress((void**)&bufX,   g_bufX);
    cudaGetSymbolAddress((void**)&bufX3,  g_bufX3);
    cudaGetSymbolAddress((void**)&bufTD,  g_bufTD);
    cudaGetSymbolAddress((void**)&bufQA,  g_bufQA);
    cudaGetSymbolAddress((void**)&bufEA,  g_bufEA);
    cudaGetSymbolAddress((void**)&predin, g_PredIn);
    cudaGetSymbolAddress((void**)&logits, g_logits);
    cudaGetSymbolAddress((void**)&predP,  g_predP);
    cudaGetSymbolAddress((void**)&Wea,    g_Wea);
    cudaGetSymbolAddress((void**)&Wd1,    g_Wd1);
    cudaGetSymbolAddress((void**)&Wd2,    g_Wd2);
    cudaGetSymbolAddress((void**)&Wro,    g_Wro);
    cudaGetSymbolAddress((void**)&Wmk,    g_Wmk);
    cudaGetSymbolAddress((void**)&bea,    g_bea);

    const int SML = (6*2048 + 128*USTR) * 4;            // 90112
    const int SMQ = (6*2048 + 128*USTR + 512) * 4;      // 92160
    const int SMG = (6*2048 + 128) * 4;                 // 49664 (3-stage ro)
    cudaFuncSetAttribute(k_fused1, cudaFuncAttributeMaxDynamicSharedMemorySize, SML);
    cudaFuncSetAttribute(k_fused2, cudaFuncAttributeMaxDynamicSharedMemorySize, SMQ);
    cudaFuncSetAttribute(k_ro,     cudaFuncAttributeMaxDynamicSharedMemorySize, SMG);

    // merged gather + weight-prep (co-run)
    k_gp<<<T_ + 2048, 128>>>(q_data, qa_data, time_data, attempt_data, hint_data, hintTotal,
                             q_emb, qa_emb, time_emb, attempt_emb, ht_emb,
                             erase_W, erase_b, add_W, add_b, diff_W, diff2_W, read_W, Mk);
    k_fused1<<<4000, 256, SML>>>(bufX, Wd1, Wd2, diff_b, diff2_b, bufTD, bufX3,
                                 q_data, attempt_data, hint_data, hintTotal,
                                 q_emb, attempt_emb, ht_emb,
                                 bufQA, Wea, bea, bufEA);
    k_fused2<<<3000, 256, SMQ>>>(bufX3, Wd1, Wmk, diff_b, bufTD,
                                 time_data, time_emb, predin, logits,
                                 bufQA, Wea, bea, bufEA);
    k_scan<<<dim3(B_, 2), 128>>>(Mv0);
    k_ro<<<dim3(4, 1000), 256, SMG>>>(predin, Wro, read_b, pred_W, predP);
    k_loss<<<(T_ + 255)/256, 256>>>(target, pred_b, out);
    k_final<<<1, 1>>>(out);
}